// round 3
// baseline (speedup 1.0000x reference)
#include <cuda_runtime.h>
#include <cuda_bf16.h>
#include <cstdint>

// ---------------- problem constants ----------------
#define NTOK   16384      // S-2 tokens
#define HIN    768        // input hidden
#define NPACK  1536       // packed gate columns: [i_f,g_f,o_f, i_b,g_b,o_b] x 256
#define HIDC   512        // enc width
#define NTAG   20
#define NCHUNK 128
#define CLEN   128        // NCHUNK*CLEN = NTOK
#define NEGV   (-10000.0f)

// ---------------- device scratch (no allocs allowed) ----------------
__device__ float d_Wt[HIN * NPACK];          // packed transposed weights [k][n]
__device__ float d_biasC[NPACK];             // b_ih + b_hh for packed cols
__device__ float d_gates[NTOK * NPACK];      // pre-activation gates
__device__ float d_enc[NTOK * HIDC];         // lstm outputs (concat f,b)
__device__ float d_feats[NTOK * NTAG];       // tag scores
__device__ float d_P[NCHUNK * NTAG * NTAG];  // per-chunk maxplus products
__device__ float d_fvs[NCHUNK * NTAG];       // chunk-start viterbi vectors
__device__ float d_finalfv[NTAG];
__device__ unsigned char d_bps[NTOK * NTAG]; // backpointers
__device__ unsigned char d_Wc[NCHUNK * NTAG];// chunk backtrack tables
__device__ unsigned char d_r[NCHUNK];        // chunk-boundary path states

// ---------------- K0: pack weights + bias ----------------
__global__ void pack_weights(const float* __restrict__ wf, const float* __restrict__ wb,
                             const float* __restrict__ bihf, const float* __restrict__ bhhf,
                             const float* __restrict__ bihb, const float* __restrict__ bhhb) {
    int idx = blockIdx.x * blockDim.x + threadIdx.x;
    if (idx >= HIN * NPACK) return;
    int k = idx / NPACK, n = idx % NPACK;
    int dir = (n >= 768) ? 1 : 0;
    int local = n - dir * 768;
    int r = local + (local < 256 ? 0 : 256);
    const float* w = dir ? wb : wf;
    d_Wt[idx] = w[r * HIN + k];
    if (k == 0) {
        d_biasC[n] = dir ? (bihb[r] + bhhb[r]) : (bihf[r] + bhhf[r]);
    }
}

// ---------------- K1: gates GEMM via packed f32x2 FFMA ----------------
#define BM 128
#define BN 128
#define BKK 16

__device__ __forceinline__ void ffma2(unsigned long long& acc, unsigned long long a,
                                      unsigned long long b) {
    asm("fma.rn.f32x2 %0, %1, %2, %0;" : "+l"(acc) : "l"(a), "l"(b));
}

__global__ __launch_bounds__(256) void gemm_gates(const float* __restrict__ A) {
    __shared__ float2 As[BKK][BM];   // A values duplicated into both lanes
    __shared__ float  Bs[BKK][BN];
    int tid = threadIdx.x;
    int bm = blockIdx.y, bn = blockIdx.x;
    const float* Ablk = A + bm * BM * HIN;
    const float* Bblk = d_Wt + bn * BN;

    unsigned long long acc[8][4];
#pragma unroll
    for (int i = 0; i < 8; i++)
#pragma unroll
        for (int j = 0; j < 4; j++) acc[i][j] = 0ull;

    int r0 = (tid >> 4) * 8;
    int c0 = (tid & 15) * 8;

    for (int kt = 0; kt < HIN; kt += BKK) {
#pragma unroll
        for (int i = 0; i < 2; i++) {
            int flat = tid + i * 256;
            int row = flat >> 2, kq = (flat & 3) * 4;
            float4 v = *(const float4*)(Ablk + row * HIN + kt + kq);
            As[kq + 0][row] = make_float2(v.x, v.x);
            As[kq + 1][row] = make_float2(v.y, v.y);
            As[kq + 2][row] = make_float2(v.z, v.z);
            As[kq + 3][row] = make_float2(v.w, v.w);
            int kr = flat >> 5, nq = (flat & 31) * 4;
            float4 w = *(const float4*)(Bblk + (kt + kr) * NPACK + nq);
            *(float4*)&Bs[kr][nq] = w;
        }
        __syncthreads();
#pragma unroll
        for (int kk = 0; kk < BKK; kk++) {
            unsigned long long a2[8], b2[4];
            ulonglong2 t0 = *(const ulonglong2*)&As[kk][r0 + 0];
            ulonglong2 t1 = *(const ulonglong2*)&As[kk][r0 + 2];
            ulonglong2 t2 = *(const ulonglong2*)&As[kk][r0 + 4];
            ulonglong2 t3 = *(const ulonglong2*)&As[kk][r0 + 6];
            a2[0] = t0.x; a2[1] = t0.y; a2[2] = t1.x; a2[3] = t1.y;
            a2[4] = t2.x; a2[5] = t2.y; a2[6] = t3.x; a2[7] = t3.y;
            ulonglong2 u0 = *(const ulonglong2*)&Bs[kk][c0];
            ulonglong2 u1 = *(const ulonglong2*)&Bs[kk][c0 + 4];
            b2[0] = u0.x; b2[1] = u0.y; b2[2] = u1.x; b2[3] = u1.y;
#pragma unroll
            for (int i = 0; i < 8; i++)
#pragma unroll
                for (int j = 0; j < 4; j++) ffma2(acc[i][j], a2[i], b2[j]);
        }
        __syncthreads();
    }
    // epilogue: add bias, store
    float bias[8];
#pragma unroll
    for (int j = 0; j < 8; j++) bias[j] = d_biasC[bn * BN + c0 + j];
#pragma unroll
    for (int i = 0; i < 8; i++) {
        int row = bm * BM + r0 + i;
        float* dst = d_gates + row * NPACK + bn * BN + c0;
        float2 f0 = *(float2*)&acc[i][0];
        float2 f1 = *(float2*)&acc[i][1];
        float2 f2 = *(float2*)&acc[i][2];
        float2 f3 = *(float2*)&acc[i][3];
        float4 v0, v1;
        v0.x = f0.x + bias[0]; v0.y = f0.y + bias[1];
        v0.z = f1.x + bias[2]; v0.w = f1.y + bias[3];
        v1.x = f2.x + bias[4]; v1.y = f2.y + bias[5];
        v1.z = f3.x + bias[6]; v1.w = f3.y + bias[7];
        *(float4*)dst = v0;
        *(float4*)(dst + 4) = v1;
    }
}

// ---------------- K2: activation -> enc ----------------
__global__ void activation_kernel() {
    int idx = blockIdx.x * blockDim.x + threadIdx.x;  // over NTOK*HIDC
    int m = idx >> 9, j = idx & 511;
    int dir = j >> 8, jj = j & 255;
    const float* gr = d_gates + m * NPACK + dir * 768 + jj;
    float iv = gr[0], gv = gr[256], ov = gr[512];
    float si = 1.f / (1.f + expf(-iv));
    float cc = si * tanhf(gv);
    float so = 1.f / (1.f + expf(-ov));
    d_enc[idx] = so * tanhf(cc);
}

// ---------------- K3: feats = enc @ w_tag^T + b_tag ----------------
// 4 warps/block; warp w owns tags [5w, 5w+5) with weights resident in registers.
// Block caches FT_TOK tokens of enc in smem.
#define FT_TOK 16
__global__ __launch_bounds__(128) void feats_kernel(const float* __restrict__ wtag,
                                                    const float* __restrict__ btag) {
    __shared__ float esm[FT_TOK][HIDC];
    int warp = threadIdx.x >> 5, lane = threadIdx.x & 31;
    float wreg[5][16];
#pragma unroll
    for (int t = 0; t < 5; t++)
#pragma unroll
        for (int q = 0; q < 16; q++)
            wreg[t][q] = wtag[(warp * 5 + t) * HIDC + q * 32 + lane];
    float bloc[5];
#pragma unroll
    for (int t = 0; t < 5; t++) bloc[t] = btag[warp * 5 + t];

    int tok0 = blockIdx.x * FT_TOK;
    const float4* src = (const float4*)(d_enc + tok0 * HIDC);
    float4* dst = (float4*)esm;
    for (int i = threadIdx.x; i < FT_TOK * HIDC / 4; i += 128) dst[i] = src[i];
    __syncthreads();

    for (int tk = 0; tk < FT_TOK; tk++) {
        float s[5] = {0.f, 0.f, 0.f, 0.f, 0.f};
#pragma unroll
        for (int q = 0; q < 16; q++) {
            float e = esm[tk][q * 32 + lane];
#pragma unroll
            for (int t = 0; t < 5; t++) s[t] += e * wreg[t][q];
        }
#pragma unroll
        for (int t = 0; t < 5; t++) {
#pragma unroll
            for (int off = 16; off > 0; off >>= 1)
                s[t] += __shfl_xor_sync(0xffffffffu, s[t], off);
        }
        if (lane == 0) {
#pragma unroll
            for (int t = 0; t < 5; t++)
                d_feats[(tok0 + tk) * NTAG + warp * 5 + t] = s[t] + bloc[t];
        }
    }
}

// ---------------- V1: per-chunk maxplus matrix products ----------------
__global__ __launch_bounds__(512) void viterbi_chunk_prod(const float* __restrict__ trans) {
    __shared__ float fsm[CLEN * NTAG];
    __shared__ float P[2][NTAG][NTAG];
    int c = blockIdx.x, tid = threadIdx.x;
    for (int i = tid; i < CLEN * NTAG; i += 512) fsm[i] = d_feats[c * CLEN * NTAG + i];
    __syncthreads();
    int j = tid / NTAG, k = tid % NTAG;
    bool act = (tid < NTAG * NTAG);
    float tr[NTAG];
    if (act) {
#pragma unroll
        for (int m = 0; m < NTAG; m++) tr[m] = trans[j * NTAG + m];
        P[0][j][k] = trans[j * NTAG + k] + fsm[j];  // t=0
    }
    __syncthreads();
    int buf = 0;
    for (int t = 1; t < CLEN; t++) {
        if (act) {
            float v = -1e30f;
#pragma unroll
            for (int m = 0; m < NTAG; m++) v = fmaxf(v, tr[m] + P[buf][m][k]);
            P[buf ^ 1][j][k] = v + fsm[t * NTAG + j];
        }
        buf ^= 1;
        __syncthreads();
    }
    if (act) d_P[c * NTAG * NTAG + j * NTAG + k] = P[buf][j][k];
}

// ---------------- V2: sequential scan with register double-buffer prefetch ----------------
__global__ void viterbi_scan() {
    __shared__ float Ps[NTAG * NTAG];
    __shared__ float fvsm[NTAG];
    int lane = threadIdx.x;  // 32 threads
    float cur[13], nx[13];
#pragma unroll
    for (int t = 0; t < 13; t++) {
        int i = lane + 32 * t;
        cur[t] = (i < NTAG * NTAG) ? d_P[i] : 0.f;
    }
    float fv = (lane == 18) ? 0.f : NEGV;  // START=18
    for (int c = 0; c < NCHUNK; c++) {
#pragma unroll
        for (int t = 0; t < 13; t++) {
            int i = lane + 32 * t;
            if (i < NTAG * NTAG) Ps[i] = cur[t];
        }
        if (lane < NTAG) { d_fvs[c * NTAG + lane] = fv; fvsm[lane] = fv; }
        __syncwarp();
        if (c + 1 < NCHUNK) {
#pragma unroll
            for (int t = 0; t < 13; t++) {
                int i = lane + 32 * t;
                nx[t] = (i < NTAG * NTAG) ? d_P[(c + 1) * NTAG * NTAG + i] : 0.f;
            }
        }
        if (lane < NTAG) {
            float nf = -1e30f;
#pragma unroll
            for (int k = 0; k < NTAG; k++) nf = fmaxf(nf, Ps[lane * NTAG + k] + fvsm[k]);
            fv = nf;
        }
        __syncwarp();
#pragma unroll
        for (int t = 0; t < 13; t++) cur[t] = nx[t];
    }
}

// ---------------- V3: per-chunk forward, emit backpointers ----------------
__global__ void viterbi_forward(const float* __restrict__ trans) {
    __shared__ float fsm[CLEN * NTAG];
    int c = blockIdx.x, lane = threadIdx.x;
    for (int i = lane; i < CLEN * NTAG; i += 32) fsm[i] = d_feats[c * CLEN * NTAG + i];
    __syncwarp();
    bool act = lane < NTAG;
    float tr[NTAG];
    if (act) {
#pragma unroll
        for (int m = 0; m < NTAG; m++) tr[m] = trans[lane * NTAG + m];
    }
    float fv = act ? d_fvs[c * NTAG + lane] : -1e30f;
    unsigned char* bp = d_bps + c * CLEN * NTAG;
    for (int t = 0; t < CLEN; t++) {
        float best = -1e30f;
        int bi = 0;
#pragma unroll
        for (int k = 0; k < NTAG; k++) {
            float v = __shfl_sync(0xffffffffu, fv, k);
            if (act) {
                v += tr[k];
                if (v > best) { best = v; bi = k; }  // first-max tiebreak
            }
        }
        if (act) {
            bp[t * NTAG + lane] = (unsigned char)bi;
            fv = best + fsm[t * NTAG + lane];
        }
    }
    if (c == NCHUNK - 1 && act) d_finalfv[lane] = fv;
}

// ---------------- B1: per-chunk backtrack composition tables ----------------
__global__ void backtrack_tables() {
    __shared__ unsigned char b[CLEN * NTAG];
    int c = blockIdx.x, lane = threadIdx.x;
    const uint4* src = (const uint4*)(d_bps + c * CLEN * NTAG);
    uint4* dstv = (uint4*)b;
    for (int i = lane; i < (CLEN * NTAG) / 16; i += 32) dstv[i] = src[i];
    __syncwarp();
    if (lane < NTAG) {
        int x = lane;
        for (int t = CLEN - 1; t >= 0; t--) x = b[t * NTAG + x];
        d_Wc[c * NTAG + lane] = (unsigned char)x;
    }
}

// ---------------- B2: terminal argmax + chunk-boundary scan ----------------
__global__ void terminal_and_scan(const float* __restrict__ trans, float* __restrict__ out) {
    __shared__ unsigned char Wsm[NCHUNK * NTAG];
    int lane = threadIdx.x;
    const uint4* src = (const uint4*)d_Wc;
    for (int i = lane; i < (NCHUNK * NTAG) / 16; i += 32) ((uint4*)Wsm)[i] = src[i];
    float term = (lane < NTAG) ? d_finalfv[lane] + trans[19 * NTAG + lane] : -1e30f;  // STOP=19
    __syncwarp();
    float best = -1e30f;
    int bi = 0;
#pragma unroll
    for (int k = 0; k < NTAG; k++) {
        float v = __shfl_sync(0xffffffffu, term, k);
        if (v > best) { best = v; bi = k; }
    }
    if (lane == 0) {
        out[0] = best;  // path_score
        int r = bi;
        d_r[NCHUNK - 1] = (unsigned char)r;
        for (int c = NCHUNK - 1; c >= 1; c--) {
            r = Wsm[c * NTAG + r];
            d_r[c - 1] = (unsigned char)r;
        }
    }
}

// ---------------- B3: per-chunk path emission ----------------
__global__ void backtrack_emit(float* __restrict__ out) {
    __shared__ unsigned char b[CLEN * NTAG];
    int c = blockIdx.x, lane = threadIdx.x;
    const uint4* src = (const uint4*)(d_bps + c * CLEN * NTAG);
    uint4* dstv = (uint4*)b;
    for (int i = lane; i < (CLEN * NTAG) / 16; i += 32) dstv[i] = src[i];
    __syncwarp();
    if (lane == 0) {
        int x = d_r[c];
        float* o = out + 1 + c * CLEN;
        for (int t = CLEN - 1; t >= 0; t--) {
            o[t] = (float)x;
            x = b[t * NTAG + x];
        }
    }
}

// ---------------- launch ----------------
extern "C" void kernel_launch(void* const* d_in, const int* in_sizes, int n_in,
                              void* d_out, int out_size) {
    const float* x      = (const float*)d_in[0];
    const float* w_ih_f = (const float*)d_in[1];
    const float* b_ih_f = (const float*)d_in[3];
    const float* b_hh_f = (const float*)d_in[4];
    const float* w_ih_b = (const float*)d_in[5];
    const float* b_ih_b = (const float*)d_in[7];
    const float* b_hh_b = (const float*)d_in[8];
    const float* w_tag  = (const float*)d_in[9];
    const float* b_tag  = (const float*)d_in[10];
    const float* trans  = (const float*)d_in[11];
    float* out = (float*)d_out;

    pack_weights<<<(HIN * NPACK + 255) / 256, 256>>>(w_ih_f, w_ih_b, b_ih_f, b_hh_f, b_ih_b, b_hh_b);

    dim3 ggrid(NPACK / BN, NTOK / BM);
    gemm_gates<<<ggrid, 256>>>(x + HIN);  // skip first token (x[0,1:-1,:])

    activation_kernel<<<(NTOK * HIDC) / 256, 256>>>();
    feats_kernel<<<NTOK / FT_TOK, 128>>>(w_tag, b_tag);

    viterbi_chunk_prod<<<NCHUNK, 512>>>(trans);
    viterbi_scan<<<1, 32>>>();
    viterbi_forward<<<NCHUNK, 32>>>(trans);
    backtrack_tables<<<NCHUNK, 32>>>();
    terminal_and_scan<<<1, 32>>>(trans, out);
    backtrack_emit<<<NCHUNK, 32>>>(out);
}

// round 5
// speedup vs baseline: 1.8804x; 1.8804x over previous
#include <cuda_runtime.h>
#include <cuda_bf16.h>
#include <cstdint>

// ---------------- problem constants ----------------
#define NTOK   16384
#define HIN    768
#define KEXT   2304      // 3*HIN: (hi,hi,lo) x (hi,lo,hi) interleave
#define NPACK  1536      // packed gate cols: [i,g,o]x256 x 2 dirs
#define HIDC   512
#define NTAG   20
#define NCHUNK 128
#define CLEN   128
#define NEGV   (-10000.0f)

// ---------------- device scratch ----------------
__device__ __nv_bfloat16 d_Aext[(size_t)NTOK * KEXT];   // 75.5 MB
__device__ __nv_bfloat16 d_Bext[(size_t)NPACK * KEXT];  // 7 MB
__device__ float d_biasC[NPACK];
__device__ float d_gates[(size_t)NTOK * NPACK];
__device__ float d_enc[(size_t)NTOK * HIDC];
__device__ float d_feats[NTOK * NTAG];
__device__ float d_P[NCHUNK * NTAG * NTAG];
__device__ float d_fvs[NCHUNK * NTAG];
__device__ float d_finalfv[NTAG];
__device__ unsigned char d_bps[NTOK * NTAG];
__device__ unsigned char d_Wc[NCHUNK * NTAG];
__device__ unsigned char d_r[NCHUNK];

// ---------------- helpers ----------------
__device__ __forceinline__ uint32_t smem_u32(const void* p) {
    uint32_t a;
    asm("{ .reg .u64 t; cvta.to.shared.u64 t, %1; cvt.u32.u64 %0, t; }" : "=r"(a) : "l"(p));
    return a;
}
#define CP_ASYNC16(dst, src) \
    asm volatile("cp.async.cg.shared.global [%0], [%1], 16;" :: "r"(dst), "l"(src))
#define CP_COMMIT() asm volatile("cp.async.commit_group;" ::: "memory")
#define CP_WAIT(n)  asm volatile("cp.async.wait_group %0;" :: "n"(n) : "memory")

__device__ __forceinline__ void ldm_x4(uint32_t* r, uint32_t addr) {
    asm volatile("ldmatrix.sync.aligned.m8n8.x4.shared.b16 {%0,%1,%2,%3}, [%4];"
                 : "=r"(r[0]), "=r"(r[1]), "=r"(r[2]), "=r"(r[3]) : "r"(addr));
}
__device__ __forceinline__ void ldm_x2(uint32_t* r, uint32_t addr) {
    asm volatile("ldmatrix.sync.aligned.m8n8.x2.shared.b16 {%0,%1}, [%2];"
                 : "=r"(r[0]), "=r"(r[1]) : "r"(addr));
}
__device__ __forceinline__ void mma16816(float* c, const uint32_t* a, const uint32_t* b) {
    asm volatile(
        "mma.sync.aligned.m16n8k16.row.col.f32.bf16.bf16.f32 "
        "{%0,%1,%2,%3}, {%4,%5,%6,%7}, {%8,%9}, {%0,%1,%2,%3};"
        : "+f"(c[0]), "+f"(c[1]), "+f"(c[2]), "+f"(c[3])
        : "r"(a[0]), "r"(a[1]), "r"(a[2]), "r"(a[3]), "r"(b[0]), "r"(b[1]));
}

__device__ __forceinline__ void split2(float f, __nv_bfloat16& h, __nv_bfloat16& l) {
    h = __float2bfloat16_rn(f);
    l = __float2bfloat16_rn(f - __bfloat162float(h));
}

// ---------------- K0a: x -> A_ext (hi,hi,lo) ----------------
__global__ void conv_x(const float* __restrict__ x) {
    int idx = blockIdx.x * blockDim.x + threadIdx.x;  // over NTOK*384
    int m = idx / 384, k2 = idx % 384;
    float2 v = *(const float2*)(x + HIN + (size_t)m * HIN + k2 * 2);
    __nv_bfloat16 h0, l0, h1, l1;
    split2(v.x, h0, l0);
    split2(v.y, h1, l1);
    __nv_bfloat16 o[6] = {h0, h0, l0, h1, h1, l1};
    uint32_t* dst = (uint32_t*)(d_Aext + (size_t)m * KEXT + k2 * 6);
    dst[0] = *(uint32_t*)&o[0];
    dst[1] = *(uint32_t*)&o[2];
    dst[2] = *(uint32_t*)&o[4];
}

// ---------------- K0b: weights -> B_ext (hi,lo,hi), bias ----------------
__global__ void pack_w(const float* __restrict__ wf, const float* __restrict__ wb,
                       const float* __restrict__ bihf, const float* __restrict__ bhhf,
                       const float* __restrict__ bihb, const float* __restrict__ bhhb) {
    int idx = blockIdx.x * blockDim.x + threadIdx.x;  // over NPACK*384
    int n = idx / 384, k2 = idx % 384;
    int dir = (n >= 768) ? 1 : 0;
    int local = n - dir * 768;
    int r = local + (local < 256 ? 0 : 256);  // skip f-gate rows
    const float* w = dir ? wb : wf;
    float2 v = *(const float2*)(w + (size_t)r * HIN + k2 * 2);
    __nv_bfloat16 h0, l0, h1, l1;
    split2(v.x, h0, l0);
    split2(v.y, h1, l1);
    __nv_bfloat16 o[6] = {h0, l0, h0, h1, l1, h1};
    uint32_t* dst = (uint32_t*)(d_Bext + (size_t)n * KEXT + k2 * 6);
    dst[0] = *(uint32_t*)&o[0];
    dst[1] = *(uint32_t*)&o[2];
    dst[2] = *(uint32_t*)&o[4];
    if (k2 == 0) d_biasC[n] = dir ? (bihb[r] + bhhb[r]) : (bihf[r] + bhhf[r]);
}

// ---------------- K1: bf16 mma.sync GEMM  gates[16384][1536] = A_ext * B_ext^T ----------------
#define BKE 32
#define ASTR 40    // padded smem row stride (elements): 80B -> ldmatrix conflict-free
#define NKI (KEXT / BKE)   // 72

__global__ __launch_bounds__(256, 1) void gemm_mma() {
    __shared__ __nv_bfloat16 Asm[2][128 * ASTR];
    __shared__ __nv_bfloat16 Bsm[2][128 * ASTR];
    int tid = threadIdx.x;
    int wid = tid >> 5, lane = tid & 31;
    int bn = blockIdx.x, bm = blockIdx.y;
    int wm = wid & 1, wn = wid >> 1;  // warp tile: 64 rows x 32 cols

    const __nv_bfloat16* Ag = d_Aext + (size_t)(bm * 128) * KEXT;
    const __nv_bfloat16* Bg = d_Bext + (size_t)(bn * 128) * KEXT;
    uint32_t sA = smem_u32(Asm), sB = smem_u32(Bsm);

    float acc[4][4][4];
#pragma unroll
    for (int i = 0; i < 4; i++)
#pragma unroll
        for (int j = 0; j < 4; j++)
#pragma unroll
            for (int q = 0; q < 4; q++) acc[i][j][q] = 0.f;

    // stage loader: 512 16B chunks for A, 512 for B
#define LOAD_STAGE(s, kt)                                                              \
    do {                                                                               \
        _Pragma("unroll")                                                              \
        for (int i_ = 0; i_ < 2; i_++) {                                               \
            int c_ = tid + i_ * 256;                                                   \
            int row_ = c_ >> 2, seg_ = c_ & 3;                                         \
            uint32_t so_ = (uint32_t)(((s) * 128 * ASTR + row_ * ASTR + seg_ * 8) * 2);\
            CP_ASYNC16(sA + so_, Ag + (size_t)row_ * KEXT + (kt) * BKE + seg_ * 8);    \
            CP_ASYNC16(sB + so_, Bg + (size_t)row_ * KEXT + (kt) * BKE + seg_ * 8);    \
        }                                                                              \
    } while (0)

    LOAD_STAGE(0, 0);
    CP_COMMIT();

    for (int kt = 0; kt < NKI; kt++) {
        int cs = kt & 1;
        if (kt + 1 < NKI) {
            LOAD_STAGE((kt + 1) & 1, kt + 1);
            CP_COMMIT();
            CP_WAIT(1);
        } else {
            CP_WAIT(0);
        }
        __syncthreads();

#pragma unroll
        for (int ks = 0; ks < 2; ks++) {
            int k0 = ks * 16;
            uint32_t afr[4][4];
#pragma unroll
            for (int i = 0; i < 4; i++) {
                int row = wm * 64 + i * 16 + (lane & 15);
                uint32_t addr = sA + (uint32_t)((cs * 128 * ASTR + row * ASTR + k0 + ((lane >> 4) * 8)) * 2);
                ldm_x4(afr[i], addr);
            }
            uint32_t bfr[4][2];
#pragma unroll
            for (int j = 0; j < 4; j++) {
                int row = wn * 32 + j * 8 + (lane & 7);
                uint32_t addr = sB + (uint32_t)((cs * 128 * ASTR + row * ASTR + k0 + (((lane >> 3) & 1) * 8)) * 2);
                ldm_x2(bfr[j], addr);
            }
#pragma unroll
            for (int i = 0; i < 4; i++)
#pragma unroll
                for (int j = 0; j < 4; j++) mma16816(acc[i][j], afr[i], bfr[j]);
        }
        __syncthreads();
    }

    // epilogue: add bias, store fp32 gates
#pragma unroll
    for (int j = 0; j < 4; j++) {
        int col = bn * 128 + wn * 32 + j * 8 + (lane & 3) * 2;
        float b0 = d_biasC[col], b1 = d_biasC[col + 1];
#pragma unroll
        for (int i = 0; i < 4; i++) {
            int row = bm * 128 + wm * 64 + i * 16 + (lane >> 2);
            float* dst = d_gates + (size_t)row * NPACK + col;
            float2 v0 = make_float2(acc[i][j][0] + b0, acc[i][j][1] + b1);
            *(float2*)dst = v0;
            float2 v1 = make_float2(acc[i][j][2] + b0, acc[i][j][3] + b1);
            *(float2*)(dst + 8 * NPACK) = v1;
        }
    }
}

// ---------------- K2: activation -> enc ----------------
__global__ void activation_kernel() {
    int idx = blockIdx.x * blockDim.x + threadIdx.x;  // over NTOK*HIDC
    int m = idx >> 9, j = idx & 511;
    int dir = j >> 8, jj = j & 255;
    const float* gr = d_gates + (size_t)m * NPACK + dir * 768 + jj;
    float iv = gr[0], gv = gr[256], ov = gr[512];
    float si = 1.f / (1.f + expf(-iv));
    float cc = si * tanhf(gv);
    float so = 1.f / (1.f + expf(-ov));
    d_enc[idx] = so * tanhf(cc);
}

// ---------------- K3: feats = enc @ w_tag^T + b_tag ----------------
#define FT_TOK 16
__global__ __launch_bounds__(128) void feats_kernel(const float* __restrict__ wtag,
                                                    const float* __restrict__ btag) {
    __shared__ float esm[FT_TOK][HIDC];
    int warp = threadIdx.x >> 5, lane = threadIdx.x & 31;
    float wreg[5][16];
#pragma unroll
    for (int t = 0; t < 5; t++)
#pragma unroll
        for (int q = 0; q < 16; q++)
            wreg[t][q] = wtag[(warp * 5 + t) * HIDC + q * 32 + lane];
    float bloc[5];
#pragma unroll
    for (int t = 0; t < 5; t++) bloc[t] = btag[warp * 5 + t];

    int tok0 = blockIdx.x * FT_TOK;
    const float4* src = (const float4*)(d_enc + (size_t)tok0 * HIDC);
    float4* dst = (float4*)esm;
    for (int i = threadIdx.x; i < FT_TOK * HIDC / 4; i += 128) dst[i] = src[i];
    __syncthreads();

    for (int tk = 0; tk < FT_TOK; tk++) {
        float s[5] = {0.f, 0.f, 0.f, 0.f, 0.f};
#pragma unroll
        for (int q = 0; q < 16; q++) {
            float e = esm[tk][q * 32 + lane];
#pragma unroll
            for (int t = 0; t < 5; t++) s[t] += e * wreg[t][q];
        }
#pragma unroll
        for (int t = 0; t < 5; t++) {
#pragma unroll
            for (int off = 16; off > 0; off >>= 1)
                s[t] += __shfl_xor_sync(0xffffffffu, s[t], off);
        }
        if (lane == 0) {
#pragma unroll
            for (int t = 0; t < 5; t++)
                d_feats[(tok0 + tk) * NTAG + warp * 5 + t] = s[t] + bloc[t];
        }
    }
}

// ---------------- V1: per-chunk maxplus products ----------------
__global__ __launch_bounds__(512) void viterbi_chunk_prod(const float* __restrict__ trans) {
    __shared__ float fsm[CLEN * NTAG];
    __shared__ float P[2][NTAG][NTAG];
    int c = blockIdx.x, tid = threadIdx.x;
    for (int i = tid; i < CLEN * NTAG; i += 512) fsm[i] = d_feats[c * CLEN * NTAG + i];
    __syncthreads();
    int j = tid / NTAG, k = tid % NTAG;
    bool act = (tid < NTAG * NTAG);
    float tr[NTAG];
    if (act) {
#pragma unroll
        for (int m = 0; m < NTAG; m++) tr[m] = trans[j * NTAG + m];
        P[0][j][k] = trans[j * NTAG + k] + fsm[j];
    }
    __syncthreads();
    int buf = 0;
    for (int t = 1; t < CLEN; t++) {
        if (act) {
            float v = -1e30f;
#pragma unroll
            for (int m = 0; m < NTAG; m++) v = fmaxf(v, tr[m] + P[buf][m][k]);
            P[buf ^ 1][j][k] = v + fsm[t * NTAG + j];
        }
        buf ^= 1;
        __syncthreads();
    }
    if (act) d_P[c * NTAG * NTAG + j * NTAG + k] = P[buf][j][k];
}

// ---------------- V2: sequential scan with prefetch ----------------
__global__ void viterbi_scan() {
    __shared__ float Ps[NTAG * NTAG];
    __shared__ float fvsm[NTAG];
    int lane = threadIdx.x;
    float cur[13], nx[13];
#pragma unroll
    for (int t = 0; t < 13; t++) {
        int i = lane + 32 * t;
        cur[t] = (i < NTAG * NTAG) ? d_P[i] : 0.f;
    }
    float fv = (lane == 18) ? 0.f : NEGV;
    for (int c = 0; c < NCHUNK; c++) {
#pragma unroll
        for (int t = 0; t < 13; t++) {
            int i = lane + 32 * t;
            if (i < NTAG * NTAG) Ps[i] = cur[t];
        }
        if (lane < NTAG) { d_fvs[c * NTAG + lane] = fv; fvsm[lane] = fv; }
        __syncwarp();
        if (c + 1 < NCHUNK) {
#pragma unroll
            for (int t = 0; t < 13; t++) {
                int i = lane + 32 * t;
                nx[t] = (i < NTAG * NTAG) ? d_P[(c + 1) * NTAG * NTAG + i] : 0.f;
            }
        }
        if (lane < NTAG) {
            float nf = -1e30f;
#pragma unroll
            for (int k = 0; k < NTAG; k++) nf = fmaxf(nf, Ps[lane * NTAG + k] + fvsm[k]);
            fv = nf;
        }
        __syncwarp();
#pragma unroll
        for (int t = 0; t < 13; t++) cur[t] = nx[t];
    }
}

// ---------------- V3: per-chunk forward, backpointers ----------------
__global__ void viterbi_forward(const float* __restrict__ trans) {
    __shared__ float fsm[CLEN * NTAG];
    int c = blockIdx.x, lane = threadIdx.x;
    for (int i = lane; i < CLEN * NTAG; i += 32) fsm[i] = d_feats[c * CLEN * NTAG + i];
    __syncwarp();
    bool act = lane < NTAG;
    float tr[NTAG];
    if (act) {
#pragma unroll
        for (int m = 0; m < NTAG; m++) tr[m] = trans[lane * NTAG + m];
    }
    float fv = act ? d_fvs[c * NTAG + lane] : -1e30f;
    unsigned char* bp = d_bps + c * CLEN * NTAG;
    for (int t = 0; t < CLEN; t++) {
        float best = -1e30f;
        int bi = 0;
#pragma unroll
        for (int k = 0; k < NTAG; k++) {
            float v = __shfl_sync(0xffffffffu, fv, k);
            if (act) {
                v += tr[k];
                if (v > best) { best = v; bi = k; }
            }
        }
        if (act) {
            bp[t * NTAG + lane] = (unsigned char)bi;
            fv = best + fsm[t * NTAG + lane];
        }
    }
    if (c == NCHUNK - 1 && act) d_finalfv[lane] = fv;
}

// ---------------- B1: chunk backtrack tables ----------------
__global__ void backtrack_tables() {
    __shared__ unsigned char b[CLEN * NTAG];
    int c = blockIdx.x, lane = threadIdx.x;
    const uint4* src = (const uint4*)(d_bps + c * CLEN * NTAG);
    uint4* dstv = (uint4*)b;
    for (int i = lane; i < (CLEN * NTAG) / 16; i += 32) dstv[i] = src[i];
    __syncwarp();
    if (lane < NTAG) {
        int x = lane;
        for (int t = CLEN - 1; t >= 0; t--) x = b[t * NTAG + x];
        d_Wc[c * NTAG + lane] = (unsigned char)x;
    }
}

// ---------------- B2: terminal argmax + boundary scan ----------------
__global__ void terminal_and_scan(const float* __restrict__ trans, float* __restrict__ out) {
    __shared__ unsigned char Wsm[NCHUNK * NTAG];
    int lane = threadIdx.x;
    const uint4* src = (const uint4*)d_Wc;
    for (int i = lane; i < (NCHUNK * NTAG) / 16; i += 32) ((uint4*)Wsm)[i] = src[i];
    float term = (lane < NTAG) ? d_finalfv[lane] + trans[19 * NTAG + lane] : -1e30f;
    __syncwarp();
    float best = -1e30f;
    int bi = 0;
#pragma unroll
    for (int k = 0; k < NTAG; k++) {
        float v = __shfl_sync(0xffffffffu, term, k);
        if (v > best) { best = v; bi = k; }
    }
    if (lane == 0) {
        out[0] = best;
        int r = bi;
        d_r[NCHUNK - 1] = (unsigned char)r;
        for (int c = NCHUNK - 1; c >= 1; c--) {
            r = Wsm[c * NTAG + r];
            d_r[c - 1] = (unsigned char)r;
        }
    }
}

// ---------------- B3: path emission ----------------
__global__ void backtrack_emit(float* __restrict__ out) {
    __shared__ unsigned char b[CLEN * NTAG];
    int c = blockIdx.x, lane = threadIdx.x;
    const uint4* src = (const uint4*)(d_bps + c * CLEN * NTAG);
    uint4* dstv = (uint4*)b;
    for (int i = lane; i < (CLEN * NTAG) / 16; i += 32) dstv[i] = src[i];
    __syncwarp();
    if (lane == 0) {
        int x = d_r[c];
        float* o = out + 1 + c * CLEN;
        for (int t = CLEN - 1; t >= 0; t--) {
            o[t] = (float)x;
            x = b[t * NTAG + x];
        }
    }
}

// ---------------- launch ----------------
extern "C" void kernel_launch(void* const* d_in, const int* in_sizes, int n_in,
                              void* d_out, int out_size) {
    const float* x      = (const float*)d_in[0];
    const float* w_ih_f = (const float*)d_in[1];
    const float* b_ih_f = (const float*)d_in[3];
    const float* b_hh_f = (const float*)d_in[4];
    const float* w_ih_b = (const float*)d_in[5];
    const float* b_ih_b = (const float*)d_in[7];
    const float* b_hh_b = (const float*)d_in[8];
    const float* w_tag  = (const float*)d_in[9];
    const float* b_tag  = (const float*)d_in[10];
    const float* trans  = (const float*)d_in[11];
    float* out = (float*)d_out;

    conv_x<<<(NTOK * 384) / 256, 256>>>(x);
    pack_w<<<(NPACK * 384) / 256, 256>>>(w_ih_f, w_ih_b, b_ih_f, b_hh_f, b_ih_b, b_hh_b);

    dim3 ggrid(NPACK / 128, NTOK / 128);
    gemm_mma<<<ggrid, 256>>>();

    activation_kernel<<<(NTOK * HIDC) / 256, 256>>>();
    feats_kernel<<<NTOK / FT_TOK, 128>>>(w_tag, b_tag);

    viterbi_chunk_prod<<<NCHUNK, 512>>>(trans);
    viterbi_scan<<<1, 32>>>();
    viterbi_forward<<<NCHUNK, 32>>>(trans);
    backtrack_tables<<<NCHUNK, 32>>>();
    terminal_and_scan<<<1, 32>>>(trans, out);
    backtrack_emit<<<NCHUNK, 32>>>(out);
}

// round 6
// speedup vs baseline: 2.0728x; 1.1023x over previous
#include <cuda_runtime.h>
#include <cuda_bf16.h>
#include <cstdint>

// ---------------- problem constants ----------------
#define NTOK   16384
#define HIN    768
#define KEXT   2304      // 3*HIN: (hi,hi,lo) x (hi,lo,hi) interleave
#define NPACK  1536      // grouped gate cols: 8 groups x 192 (= i|g|o x 64 j)
#define HIDC   512
#define NTAG   20
#define NCHUNK 128
#define CLEN   128
#define NEGV   (-10000.0f)

// ---------------- device scratch ----------------
__device__ __nv_bfloat16 d_Aext[(size_t)NTOK * KEXT];   // 75.5 MB
__device__ __nv_bfloat16 d_Bext[(size_t)NPACK * KEXT];  // 7 MB
__device__ float d_biasG[NPACK];
__device__ float d_enc[(size_t)NTOK * HIDC];
__device__ float d_feats[NTOK * NTAG];
__device__ float d_P[NCHUNK * NTAG * NTAG];
__device__ float d_fvs[NCHUNK * NTAG];
__device__ float d_finalfv[NTAG];
__device__ unsigned char d_bps[NTOK * NTAG];
__device__ unsigned char d_Wc[NCHUNK * NTAG];
__device__ unsigned char d_r[NCHUNK];

// ---------------- helpers ----------------
__device__ __forceinline__ uint32_t smem_u32(const void* p) {
    uint32_t a;
    asm("{ .reg .u64 t; cvta.to.shared.u64 t, %1; cvt.u32.u64 %0, t; }" : "=r"(a) : "l"(p));
    return a;
}
#define CP_ASYNC16(dst, src) \
    asm volatile("cp.async.cg.shared.global [%0], [%1], 16;" :: "r"(dst), "l"(src))
#define CP_COMMIT() asm volatile("cp.async.commit_group;" ::: "memory")
#define CP_WAIT(n)  asm volatile("cp.async.wait_group %0;" :: "n"(n) : "memory")

__device__ __forceinline__ void ldm_x4(uint32_t* r, uint32_t addr) {
    asm volatile("ldmatrix.sync.aligned.m8n8.x4.shared.b16 {%0,%1,%2,%3}, [%4];"
                 : "=r"(r[0]), "=r"(r[1]), "=r"(r[2]), "=r"(r[3]) : "r"(addr));
}
__device__ __forceinline__ void mma16816(float* c, const uint32_t* a, uint32_t b0, uint32_t b1) {
    asm volatile(
        "mma.sync.aligned.m16n8k16.row.col.f32.bf16.bf16.f32 "
        "{%0,%1,%2,%3}, {%4,%5,%6,%7}, {%8,%9}, {%0,%1,%2,%3};"
        : "+f"(c[0]), "+f"(c[1]), "+f"(c[2]), "+f"(c[3])
        : "r"(a[0]), "r"(a[1]), "r"(a[2]), "r"(a[3]), "r"(b0), "r"(b1));
}
__device__ __forceinline__ void split2(float f, __nv_bfloat16& h, __nv_bfloat16& l) {
    h = __float2bfloat16_rn(f);
    l = __float2bfloat16_rn(f - __bfloat162float(h));
}

// ---------------- K0a: x -> A_ext (hi,hi,lo) ----------------
__global__ void conv_x(const float* __restrict__ x) {
    int idx = blockIdx.x * blockDim.x + threadIdx.x;  // over NTOK*384
    int m = idx / 384, k2 = idx % 384;
    float2 v = *(const float2*)(x + HIN + (size_t)m * HIN + k2 * 2);
    __nv_bfloat16 h0, l0, h1, l1;
    split2(v.x, h0, l0);
    split2(v.y, h1, l1);
    __nv_bfloat16 o[6] = {h0, h0, l0, h1, h1, l1};
    uint32_t* dst = (uint32_t*)(d_Aext + (size_t)m * KEXT + k2 * 6);
    dst[0] = *(uint32_t*)&o[0];
    dst[1] = *(uint32_t*)&o[2];
    dst[2] = *(uint32_t*)&o[4];
}

// ---------------- K0b: weights -> grouped B_ext (hi,lo,hi), grouped bias ----------------
// grouped col n: group g = n/192 (dir = g>>2, jblk = g&3), cg = n%192,
//   gate = cg/64 (0:i 1:g 2:o), jj = cg%64; src w row = gateoff + jblk*64 + jj
__global__ void pack_w(const float* __restrict__ wf, const float* __restrict__ wb,
                       const float* __restrict__ bihf, const float* __restrict__ bhhf,
                       const float* __restrict__ bihb, const float* __restrict__ bhhb) {
    int idx = blockIdx.x * blockDim.x + threadIdx.x;  // over NPACK*384
    int n = idx / 384, k2 = idx % 384;
    int g = n / 192, cg = n % 192;
    int dir = g >> 2, jblk = g & 3;
    int gate = cg / 64, jj = cg % 64;
    int gateoff = (gate == 0) ? 0 : (gate == 1 ? 512 : 768);
    int r = gateoff + jblk * 64 + jj;
    const float* w = dir ? wb : wf;
    float2 v = *(const float2*)(w + (size_t)r * HIN + k2 * 2);
    __nv_bfloat16 h0, l0, h1, l1;
    split2(v.x, h0, l0);
    split2(v.y, h1, l1);
    __nv_bfloat16 o[6] = {h0, l0, h0, h1, l1, h1};
    uint32_t* dst = (uint32_t*)(d_Bext + (size_t)n * KEXT + k2 * 6);
    dst[0] = *(uint32_t*)&o[0];
    dst[1] = *(uint32_t*)&o[2];
    dst[2] = *(uint32_t*)&o[4];
    if (k2 == 0) {
        const float* bih = dir ? bihb : bihf;
        const float* bhh = dir ? bhhb : bhhf;
        d_biasG[n] = bih[r] + bhh[r];
    }
}

// ---------------- K1: fused bf16 mma GEMM + LSTM activation -> enc ----------------
#define BKE 32
#define ASTR 40
#define NKI (KEXT / BKE)         // 72
#define SA_STAGE (128 * ASTR)    // elements per A stage
#define SB_STAGE (192 * ASTR)
#define GSMEM ((3 * SA_STAGE + 3 * SB_STAGE) * 2)   // 76800 bytes
#define EXSTR 196

__global__ __launch_bounds__(256, 1) void gemm_fused() {
    extern __shared__ char dsm[];
    __nv_bfloat16* Asm = (__nv_bfloat16*)dsm;
    __nv_bfloat16* Bsm = Asm + 3 * SA_STAGE;
    float* Ex = (float*)dsm;                 // epilogue overlay: 64 x EXSTR fp32
    int tid = threadIdx.x;
    int wid = tid >> 5, lane = tid & 31;
    int wm = wid >> 2, wn = wid & 3;         // warp tile 64 x 48
    int g = blockIdx.x, bm = blockIdx.y;

    const __nv_bfloat16* Ag = d_Aext + (size_t)(bm * 128) * KEXT;
    const __nv_bfloat16* Bg = d_Bext + (size_t)(g * 192) * KEXT;
    uint32_t sA = smem_u32(Asm), sB = smem_u32(Bsm);

    float acc[4][6][4];
#pragma unroll
    for (int i = 0; i < 4; i++)
#pragma unroll
        for (int j = 0; j < 6; j++)
#pragma unroll
            for (int q = 0; q < 4; q++) acc[i][j][q] = 0.f;

#define LOAD_STAGE(s, kt)                                                                \
    do {                                                                                 \
        _Pragma("unroll")                                                                \
        for (int i_ = 0; i_ < 2; i_++) {                                                 \
            int c_ = tid + i_ * 256;                                                     \
            int row_ = c_ >> 2, seg_ = c_ & 3;                                           \
            CP_ASYNC16(sA + (uint32_t)(((s) * SA_STAGE + row_ * ASTR + seg_ * 8) * 2),   \
                       Ag + (size_t)row_ * KEXT + (kt) * BKE + seg_ * 8);                \
        }                                                                                \
        _Pragma("unroll")                                                                \
        for (int i_ = 0; i_ < 3; i_++) {                                                 \
            int c_ = tid + i_ * 256;                                                     \
            int row_ = c_ >> 2, seg_ = c_ & 3;                                           \
            CP_ASYNC16(sB + (uint32_t)(((s) * SB_STAGE + row_ * ASTR + seg_ * 8) * 2),   \
                       Bg + (size_t)row_ * KEXT + (kt) * BKE + seg_ * 8);                \
        }                                                                                \
    } while (0)

    LOAD_STAGE(0, 0);
    CP_COMMIT();
    LOAD_STAGE(1, 1);
    CP_COMMIT();

    int cs = 0;
    for (int kt = 0; kt < NKI; kt++) {
        if (kt + 2 < NKI) {
            int ns = (kt + 2) % 3;
            LOAD_STAGE(ns, kt + 2);
            CP_COMMIT();
            CP_WAIT(2);
        } else {
            CP_WAIT(0);
        }
        __syncthreads();

#pragma unroll
        for (int ks = 0; ks < 2; ks++) {
            int k0 = ks * 16;
            uint32_t afr[4][4];
#pragma unroll
            for (int i = 0; i < 4; i++) {
                int row = wm * 64 + i * 16 + (lane & 15);
                uint32_t addr = sA + (uint32_t)((cs * SA_STAGE + row * ASTR + k0 + ((lane >> 4) * 8)) * 2);
                ldm_x4(afr[i], addr);
            }
            uint32_t bfr[3][4];
#pragma unroll
            for (int p = 0; p < 3; p++) {
                int row = wn * 48 + p * 16 + (lane & 15);
                uint32_t addr = sB + (uint32_t)((cs * SB_STAGE + row * ASTR + k0 + ((lane >> 4) * 8)) * 2);
                ldm_x4(bfr[p], addr);
            }
#pragma unroll
            for (int i = 0; i < 4; i++)
#pragma unroll
                for (int p = 0; p < 3; p++) {
                    mma16816(acc[i][2 * p + 0], afr[i], bfr[p][0], bfr[p][2]);
                    mma16816(acc[i][2 * p + 1], afr[i], bfr[p][1], bfr[p][3]);
                }
        }
        __syncthreads();
        cs = (cs + 1 == 3) ? 0 : cs + 1;
    }

    // ---- fused epilogue: bias + LSTM activation -> enc ----
    float2 bias[6];
#pragma unroll
    for (int jt = 0; jt < 6; jt++) {
        int col = g * 192 + wn * 48 + jt * 8 + (lane & 3) * 2;
        bias[jt] = *(const float2*)(d_biasG + col);
    }
    int dir = g >> 2, jblk = g & 3;
    int base = dir * 256 + jblk * 64;

#pragma unroll
    for (int ch = 0; ch < 2; ch++) {
        if (wm == ch) {
#pragma unroll
            for (int i = 0; i < 4; i++) {
                int r = i * 16 + (lane >> 2);
                int cbase = wn * 48 + (lane & 3) * 2;
#pragma unroll
                for (int jt = 0; jt < 6; jt++) {
                    int c = cbase + jt * 8;
                    Ex[r * EXSTR + c]           = acc[i][jt][0] + bias[jt].x;
                    Ex[r * EXSTR + c + 1]       = acc[i][jt][1] + bias[jt].y;
                    Ex[(r + 8) * EXSTR + c]     = acc[i][jt][2] + bias[jt].x;
                    Ex[(r + 8) * EXSTR + c + 1] = acc[i][jt][3] + bias[jt].y;
                }
            }
        }
        __syncthreads();
#pragma unroll
        for (int u = 0; u < 16; u++) {
            int idx = u * 256 + tid;
            int r = idx >> 6, j = idx & 63;
            float iv = Ex[r * EXSTR + j];
            float gv = Ex[r * EXSTR + 64 + j];
            float ov = Ex[r * EXSTR + 128 + j];
            float si = 1.f / (1.f + expf(-iv));
            float cc = si * tanhf(gv);
            float so = 1.f / (1.f + expf(-ov));
            d_enc[(size_t)(bm * 128 + ch * 64 + r) * HIDC + base + j] = so * tanhf(cc);
        }
        __syncthreads();
    }
}

// ---------------- K3: feats = enc @ w_tag^T + b_tag ----------------
#define FT_TOK 16
__global__ __launch_bounds__(128) void feats_kernel(const float* __restrict__ wtag,
                                                    const float* __restrict__ btag) {
    __shared__ float esm[FT_TOK][HIDC];
    int warp = threadIdx.x >> 5, lane = threadIdx.x & 31;
    float wreg[5][16];
#pragma unroll
    for (int t = 0; t < 5; t++)
#pragma unroll
        for (int q = 0; q < 16; q++)
            wreg[t][q] = wtag[(warp * 5 + t) * HIDC + q * 32 + lane];
    float bloc[5];
#pragma unroll
    for (int t = 0; t < 5; t++) bloc[t] = btag[warp * 5 + t];

    int tok0 = blockIdx.x * FT_TOK;
    const float4* src = (const float4*)(d_enc + (size_t)tok0 * HIDC);
    float4* dst = (float4*)esm;
    for (int i = threadIdx.x; i < FT_TOK * HIDC / 4; i += 128) dst[i] = src[i];
    __syncthreads();

    for (int tk = 0; tk < FT_TOK; tk++) {
        float s[5] = {0.f, 0.f, 0.f, 0.f, 0.f};
#pragma unroll
        for (int q = 0; q < 16; q++) {
            float e = esm[tk][q * 32 + lane];
#pragma unroll
            for (int t = 0; t < 5; t++) s[t] += e * wreg[t][q];
        }
#pragma unroll
        for (int t = 0; t < 5; t++) {
#pragma unroll
            for (int off = 16; off > 0; off >>= 1)
                s[t] += __shfl_xor_sync(0xffffffffu, s[t], off);
        }
        if (lane == 0) {
#pragma unroll
            for (int t = 0; t < 5; t++)
                d_feats[(tok0 + tk) * NTAG + warp * 5 + t] = s[t] + bloc[t];
        }
    }
}

// ---------------- V1: per-chunk maxplus products ----------------
__global__ __launch_bounds__(512) void viterbi_chunk_prod(const float* __restrict__ trans) {
    __shared__ float fsm[CLEN * NTAG];
    __shared__ float P[2][NTAG][NTAG];
    int c = blockIdx.x, tid = threadIdx.x;
    for (int i = tid; i < CLEN * NTAG; i += 512) fsm[i] = d_feats[c * CLEN * NTAG + i];
    __syncthreads();
    int j = tid / NTAG, k = tid % NTAG;
    bool act = (tid < NTAG * NTAG);
    float tr[NTAG];
    if (act) {
#pragma unroll
        for (int m = 0; m < NTAG; m++) tr[m] = trans[j * NTAG + m];
        P[0][j][k] = trans[j * NTAG + k] + fsm[j];
    }
    __syncthreads();
    int buf = 0;
    for (int t = 1; t < CLEN; t++) {
        if (act) {
            float v = -1e30f;
#pragma unroll
            for (int m = 0; m < NTAG; m++) v = fmaxf(v, tr[m] + P[buf][m][k]);
            P[buf ^ 1][j][k] = v + fsm[t * NTAG + j];
        }
        buf ^= 1;
        __syncthreads();
    }
    if (act) d_P[c * NTAG * NTAG + j * NTAG + k] = P[buf][j][k];
}

// ---------------- V2: sequential scan with prefetch ----------------
__global__ void viterbi_scan() {
    __shared__ float Ps[NTAG * NTAG];
    __shared__ float fvsm[NTAG];
    int lane = threadIdx.x;
    float cur[13], nx[13];
#pragma unroll
    for (int t = 0; t < 13; t++) {
        int i = lane + 32 * t;
        cur[t] = (i < NTAG * NTAG) ? d_P[i] : 0.f;
    }
    float fv = (lane == 18) ? 0.f : NEGV;
    for (int c = 0; c < NCHUNK; c++) {
#pragma unroll
        for (int t = 0; t < 13; t++) {
            int i = lane + 32 * t;
            if (i < NTAG * NTAG) Ps[i] = cur[t];
        }
        if (lane < NTAG) { d_fvs[c * NTAG + lane] = fv; fvsm[lane] = fv; }
        __syncwarp();
        if (c + 1 < NCHUNK) {
#pragma unroll
            for (int t = 0; t < 13; t++) {
                int i = lane + 32 * t;
                nx[t] = (i < NTAG * NTAG) ? d_P[(c + 1) * NTAG * NTAG + i] : 0.f;
            }
        }
        if (lane < NTAG) {
            float nf = -1e30f;
#pragma unroll
            for (int k = 0; k < NTAG; k++) nf = fmaxf(nf, Ps[lane * NTAG + k] + fvsm[k]);
            fv = nf;
        }
        __syncwarp();
#pragma unroll
        for (int t = 0; t < 13; t++) cur[t] = nx[t];
    }
}

// ---------------- V3: per-chunk forward, backpointers ----------------
__global__ void viterbi_forward(const float* __restrict__ trans) {
    __shared__ float fsm[CLEN * NTAG];
    int c = blockIdx.x, lane = threadIdx.x;
    for (int i = lane; i < CLEN * NTAG; i += 32) fsm[i] = d_feats[c * CLEN * NTAG + i];
    __syncwarp();
    bool act = lane < NTAG;
    float tr[NTAG];
    if (act) {
#pragma unroll
        for (int m = 0; m < NTAG; m++) tr[m] = trans[lane * NTAG + m];
    }
    float fv = act ? d_fvs[c * NTAG + lane] : -1e30f;
    unsigned char* bp = d_bps + c * CLEN * NTAG;
    for (int t = 0; t < CLEN; t++) {
        float best = -1e30f;
        int bi = 0;
#pragma unroll
        for (int k = 0; k < NTAG; k++) {
            float v = __shfl_sync(0xffffffffu, fv, k);
            if (act) {
                v += tr[k];
                if (v > best) { best = v; bi = k; }
            }
        }
        if (act) {
            bp[t * NTAG + lane] = (unsigned char)bi;
            fv = best + fsm[t * NTAG + lane];
        }
    }
    if (c == NCHUNK - 1 && act) d_finalfv[lane] = fv;
}

// ---------------- B1: chunk backtrack tables ----------------
__global__ void backtrack_tables() {
    __shared__ unsigned char b[CLEN * NTAG];
    int c = blockIdx.x, lane = threadIdx.x;
    const uint4* src = (const uint4*)(d_bps + c * CLEN * NTAG);
    uint4* dstv = (uint4*)b;
    for (int i = lane; i < (CLEN * NTAG) / 16; i += 32) dstv[i] = src[i];
    __syncwarp();
    if (lane < NTAG) {
        int x = lane;
        for (int t = CLEN - 1; t >= 0; t--) x = b[t * NTAG + x];
        d_Wc[c * NTAG + lane] = (unsigned char)x;
    }
}

// ---------------- B2: terminal argmax + boundary scan ----------------
__global__ void terminal_and_scan(const float* __restrict__ trans, float* __restrict__ out) {
    __shared__ unsigned char Wsm[NCHUNK * NTAG];
    int lane = threadIdx.x;
    const uint4* src = (const uint4*)d_Wc;
    for (int i = lane; i < (NCHUNK * NTAG) / 16; i += 32) ((uint4*)Wsm)[i] = src[i];
    float term = (lane < NTAG) ? d_finalfv[lane] + trans[19 * NTAG + lane] : -1e30f;
    __syncwarp();
    float best = -1e30f;
    int bi = 0;
#pragma unroll
    for (int k = 0; k < NTAG; k++) {
        float v = __shfl_sync(0xffffffffu, term, k);
        if (v > best) { best = v; bi = k; }
    }
    if (lane == 0) {
        out[0] = best;
        int r = bi;
        d_r[NCHUNK - 1] = (unsigned char)r;
        for (int c = NCHUNK - 1; c >= 1; c--) {
            r = Wsm[c * NTAG + r];
            d_r[c - 1] = (unsigned char)r;
        }
    }
}

// ---------------- B3: path emission ----------------
__global__ void backtrack_emit(float* __restrict__ out) {
    __shared__ unsigned char b[CLEN * NTAG];
    int c = blockIdx.x, lane = threadIdx.x;
    const uint4* src = (const uint4*)(d_bps + c * CLEN * NTAG);
    uint4* dstv = (uint4*)b;
    for (int i = lane; i < (CLEN * NTAG) / 16; i += 32) dstv[i] = src[i];
    __syncwarp();
    if (lane == 0) {
        int x = d_r[c];
        float* o = out + 1 + c * CLEN;
        for (int t = CLEN - 1; t >= 0; t--) {
            o[t] = (float)x;
            x = b[t * NTAG + x];
        }
    }
}

// ---------------- launch ----------------
extern "C" void kernel_launch(void* const* d_in, const int* in_sizes, int n_in,
                              void* d_out, int out_size) {
    const float* x      = (const float*)d_in[0];
    const float* w_ih_f = (const float*)d_in[1];
    const float* b_ih_f = (const float*)d_in[3];
    const float* b_hh_f = (const float*)d_in[4];
    const float* w_ih_b = (const float*)d_in[5];
    const float* b_ih_b = (const float*)d_in[7];
    const float* b_hh_b = (const float*)d_in[8];
    const float* w_tag  = (const float*)d_in[9];
    const float* b_tag  = (const float*)d_in[10];
    const float* trans  = (const float*)d_in[11];
    float* out = (float*)d_out;

    cudaFuncSetAttribute(gemm_fused, cudaFuncAttributeMaxDynamicSharedMemorySize, GSMEM);

    conv_x<<<(NTOK * 384) / 256, 256>>>(x);
    pack_w<<<(NPACK * 384) / 256, 256>>>(w_ih_f, w_ih_b, b_ih_f, b_hh_f, b_ih_b, b_hh_b);

    dim3 ggrid(NPACK / 192, NTOK / 128);
    gemm_fused<<<ggrid, 256, GSMEM>>>();

    feats_kernel<<<NTOK / FT_TOK, 128>>>(w_tag, b_tag);

    viterbi_chunk_prod<<<NCHUNK, 512>>>(trans);
    viterbi_scan<<<1, 32>>>();
    viterbi_forward<<<NCHUNK, 32>>>(trans);
    backtrack_tables<<<NCHUNK, 32>>>();
    terminal_and_scan<<<1, 32>>>(trans, out);
    backtrack_emit<<<NCHUNK, 32>>>(out);
}

// round 7
// speedup vs baseline: 2.2055x; 1.0640x over previous
#include <cuda_runtime.h>
#include <cuda_bf16.h>
#include <cstdint>

// ---------------- problem constants ----------------
#define NTOK   16384
#define HIN    768
#define NPACK  1536      // grouped gate cols: 8 groups x 192 (= i|g|o x 64 j)
#define HIDC   512
#define NTAG   20
#define NCHUNK 128
#define CLEN   128
#define NEGV   (-10000.0f)

// ---------------- device scratch ----------------
__device__ __nv_bfloat16 d_Ahi[(size_t)NTOK * HIN];
__device__ __nv_bfloat16 d_Alo[(size_t)NTOK * HIN];
__device__ __nv_bfloat16 d_Bhi[(size_t)NPACK * HIN];   // grouped rows, K-major
__device__ __nv_bfloat16 d_Blo[(size_t)NPACK * HIN];
__device__ float d_biasG[NPACK];
__device__ float d_enc[(size_t)NTOK * HIDC];
__device__ float d_feats[NTOK * NTAG];
__device__ float d_P[NCHUNK * NTAG * NTAG];
__device__ float d_fvs[NCHUNK * NTAG];
__device__ float d_finalfv[NTAG];
__device__ unsigned char d_bps[NTOK * NTAG];
__device__ unsigned char d_Wc[NCHUNK * NTAG];
__device__ unsigned char d_r[NCHUNK];

// ---------------- helpers ----------------
__device__ __forceinline__ uint32_t smem_u32(const void* p) {
    uint32_t a;
    asm("{ .reg .u64 t; cvta.to.shared.u64 t, %1; cvt.u32.u64 %0, t; }" : "=r"(a) : "l"(p));
    return a;
}
#define CP_ASYNC16(dst, src) \
    asm volatile("cp.async.cg.shared.global [%0], [%1], 16;" :: "r"(dst), "l"(src))
#define CP_COMMIT() asm volatile("cp.async.commit_group;" ::: "memory")
#define CP_WAIT(n)  asm volatile("cp.async.wait_group %0;" :: "n"(n) : "memory")

__device__ __forceinline__ void ldm_x4(uint32_t* r, uint32_t addr) {
    asm volatile("ldmatrix.sync.aligned.m8n8.x4.shared.b16 {%0,%1,%2,%3}, [%4];"
                 : "=r"(r[0]), "=r"(r[1]), "=r"(r[2]), "=r"(r[3]) : "r"(addr));
}
__device__ __forceinline__ void mma16816(float* c, const uint32_t* a, uint32_t b0, uint32_t b1) {
    asm volatile(
        "mma.sync.aligned.m16n8k16.row.col.f32.bf16.bf16.f32 "
        "{%0,%1,%2,%3}, {%4,%5,%6,%7}, {%8,%9}, {%0,%1,%2,%3};"
        : "+f"(c[0]), "+f"(c[1]), "+f"(c[2]), "+f"(c[3])
        : "r"(a[0]), "r"(a[1]), "r"(a[2]), "r"(a[3]), "r"(b0), "r"(b1));
}
__device__ __forceinline__ void split2(float f, __nv_bfloat16& h, __nv_bfloat16& l) {
    h = __float2bfloat16_rn(f);
    l = __float2bfloat16_rn(f - __bfloat162float(h));
}

// ---------------- K0a: x -> Ahi/Alo ----------------
__global__ void conv_x(const float* __restrict__ x) {
    int idx = blockIdx.x * blockDim.x + threadIdx.x;  // over NTOK*HIN/4
    float4 v = *(const float4*)(x + HIN + (size_t)idx * 4);  // skip token 0
    float f[4] = {v.x, v.y, v.z, v.w};
    __nv_bfloat16 hi[4], lo[4];
#pragma unroll
    for (int i = 0; i < 4; i++) split2(f[i], hi[i], lo[i]);
    *(ulonglong1*)(d_Ahi + (size_t)idx * 4) = *(ulonglong1*)hi;
    *(ulonglong1*)(d_Alo + (size_t)idx * 4) = *(ulonglong1*)lo;
}

// ---------------- K0b: weights -> grouped Bhi/Blo + bias ----------------
// grouped row n: g = n/192 (dir=g>>2, jblk=g&3), cg=n%192, gate=cg/64, jj=cg%64
__global__ void pack_w(const float* __restrict__ wf, const float* __restrict__ wb,
                       const float* __restrict__ bihf, const float* __restrict__ bhhf,
                       const float* __restrict__ bihb, const float* __restrict__ bhhb) {
    int idx = blockIdx.x * blockDim.x + threadIdx.x;  // over NPACK*HIN/4
    int n = idx / (HIN / 4);
    int kq = (idx % (HIN / 4)) * 4;
    int g = n / 192, cg = n % 192;
    int dir = g >> 2, jblk = g & 3;
    int gate = cg / 64, jj = cg % 64;
    int gateoff = (gate == 0) ? 0 : (gate == 1 ? 512 : 768);
    int r = gateoff + jblk * 64 + jj;
    const float* w = dir ? wb : wf;
    float4 v = *(const float4*)(w + (size_t)r * HIN + kq);
    float f[4] = {v.x, v.y, v.z, v.w};
    __nv_bfloat16 hi[4], lo[4];
#pragma unroll
    for (int i = 0; i < 4; i++) split2(f[i], hi[i], lo[i]);
    *(ulonglong1*)(d_Bhi + (size_t)n * HIN + kq) = *(ulonglong1*)hi;
    *(ulonglong1*)(d_Blo + (size_t)n * HIN + kq) = *(ulonglong1*)lo;
    if (kq == 0) {
        const float* bih = dir ? bihb : bihf;
        const float* bhh = dir ? bhhb : bhhf;
        d_biasG[n] = bih[r] + bhh[r];
    }
}

// ---------------- K1: fused bf16 mma GEMM (3-term split) + LSTM activation ----------------
#define BKE 32
#define ASTR 40
#define NKI 72                    // 3 passes x 24 k-tiles of 32 over K=768
#define SA_STAGE (128 * ASTR)
#define SB_STAGE (192 * ASTR)
#define GSMEM ((4 * SA_STAGE + 4 * SB_STAGE) * 2)   // 102400 B
#define EXSTR 196

// phase q = kt/24: 0:(Ahi,Bhi) 1:(Ahi,Blo) 2:(Alo,Bhi); offset (kt%24)*32
#define KSRC(kt, pa, pb)                                                        \
    do {                                                                        \
        int q_ = (kt) / 24, off_ = ((kt) % 24) * BKE;                           \
        pa = (q_ == 2 ? d_Alo : d_Ahi) + (size_t)(bm * 128) * HIN + off_;       \
        pb = (q_ == 1 ? d_Blo : d_Bhi) + (size_t)(g * 192) * HIN + off_;        \
    } while (0)

__global__ __launch_bounds__(256, 1) void gemm_fused() {
    extern __shared__ char dsm[];
    __nv_bfloat16* Asm = (__nv_bfloat16*)dsm;
    __nv_bfloat16* Bsm = Asm + 4 * SA_STAGE;
    float* Ex = (float*)dsm;                 // epilogue overlay: 64 x EXSTR fp32
    int tid = threadIdx.x;
    int wid = tid >> 5, lane = tid & 31;
    int wm = wid >> 2, wn = wid & 3;         // warp tile 64 x 48
    int g = blockIdx.x, bm = blockIdx.y;

    uint32_t sA = smem_u32(Asm), sB = smem_u32(Bsm);

    float acc[4][6][4];
#pragma unroll
    for (int i = 0; i < 4; i++)
#pragma unroll
        for (int j = 0; j < 6; j++)
#pragma unroll
            for (int q = 0; q < 4; q++) acc[i][j][q] = 0.f;

#define LOAD_STAGE(s, pa, pb)                                                            \
    do {                                                                                 \
        _Pragma("unroll")                                                                \
        for (int i_ = 0; i_ < 2; i_++) {                                                 \
            int c_ = tid + i_ * 256;                                                     \
            int row_ = c_ >> 2, seg_ = c_ & 3;                                           \
            CP_ASYNC16(sA + (uint32_t)(((s) * SA_STAGE + row_ * ASTR + seg_ * 8) * 2),   \
                       (pa) + (size_t)row_ * HIN + seg_ * 8);                            \
        }                                                                                \
        _Pragma("unroll")                                                                \
        for (int i_ = 0; i_ < 3; i_++) {                                                 \
            int c_ = tid + i_ * 256;                                                     \
            int row_ = c_ >> 2, seg_ = c_ & 3;                                           \
            CP_ASYNC16(sB + (uint32_t)(((s) * SB_STAGE + row_ * ASTR + seg_ * 8) * 2),   \
                       (pb) + (size_t)row_ * HIN + seg_ * 8);                            \
        }                                                                                \
    } while (0)

    {
        const __nv_bfloat16 *pa, *pb;
        KSRC(0, pa, pb); LOAD_STAGE(0, pa, pb); CP_COMMIT();
        KSRC(1, pa, pb); LOAD_STAGE(1, pa, pb); CP_COMMIT();
        KSRC(2, pa, pb); LOAD_STAGE(2, pa, pb); CP_COMMIT();
    }

    for (int kt = 0; kt < NKI; kt++) {
        if (kt < NKI - 2) { CP_WAIT(2); }
        else if (kt == NKI - 2) { CP_WAIT(1); }
        else { CP_WAIT(0); }
        __syncthreads();
        int cs = kt & 3;

#pragma unroll
        for (int ks = 0; ks < 2; ks++) {
            int k0 = ks * 16;
            uint32_t afr[4][4];
#pragma unroll
            for (int i = 0; i < 4; i++) {
                int row = wm * 64 + i * 16 + (lane & 15);
                uint32_t addr = sA + (uint32_t)((cs * SA_STAGE + row * ASTR + k0 + ((lane >> 4) * 8)) * 2);
                ldm_x4(afr[i], addr);
            }
            uint32_t bfr[3][4];
#pragma unroll
            for (int p = 0; p < 3; p++) {
                int row = wn * 48 + p * 16 + (lane & 15);
                uint32_t addr = sB + (uint32_t)((cs * SB_STAGE + row * ASTR + k0 + ((lane >> 4) * 8)) * 2);
                ldm_x4(bfr[p], addr);
            }
#pragma unroll
            for (int i = 0; i < 4; i++)
#pragma unroll
                for (int p = 0; p < 3; p++) {
                    mma16816(acc[i][2 * p + 0], afr[i], bfr[p][0], bfr[p][2]);
                    mma16816(acc[i][2 * p + 1], afr[i], bfr[p][1], bfr[p][3]);
                }
        }

        if (kt + 3 < NKI) {
            const __nv_bfloat16 *pa, *pb;
            KSRC(kt + 3, pa, pb);
            LOAD_STAGE((kt + 3) & 3, pa, pb);
            CP_COMMIT();
        }
    }
    __syncthreads();

    // ---- fused epilogue: bias + LSTM activation -> enc ----
    float2 bias[6];
#pragma unroll
    for (int jt = 0; jt < 6; jt++) {
        int col = g * 192 + wn * 48 + jt * 8 + (lane & 3) * 2;
        bias[jt] = *(const float2*)(d_biasG + col);
    }
    int dir = g >> 2, jblk = g & 3;
    int base = dir * 256 + jblk * 64;

#pragma unroll
    for (int ch = 0; ch < 2; ch++) {
        if (wm == ch) {
#pragma unroll
            for (int i = 0; i < 4; i++) {
                int r = i * 16 + (lane >> 2);
                int cbase = wn * 48 + (lane & 3) * 2;
#pragma unroll
                for (int jt = 0; jt < 6; jt++) {
                    int c = cbase + jt * 8;
                    Ex[r * EXSTR + c]           = acc[i][jt][0] + bias[jt].x;
                    Ex[r * EXSTR + c + 1]       = acc[i][jt][1] + bias[jt].y;
                    Ex[(r + 8) * EXSTR + c]     = acc[i][jt][2] + bias[jt].x;
                    Ex[(r + 8) * EXSTR + c + 1] = acc[i][jt][3] + bias[jt].y;
                }
            }
        }
        __syncthreads();
#pragma unroll
        for (int u = 0; u < 16; u++) {
            int idx = u * 256 + tid;
            int r = idx >> 6, j = idx & 63;
            float iv = Ex[r * EXSTR + j];
            float gv = Ex[r * EXSTR + 64 + j];
            float ov = Ex[r * EXSTR + 128 + j];
            float si = 1.f / (1.f + expf(-iv));
            float cc = si * tanhf(gv);
            float so = 1.f / (1.f + expf(-ov));
            d_enc[(size_t)(bm * 128 + ch * 64 + r) * HIDC + base + j] = so * tanhf(cc);
        }
        __syncthreads();
    }
}

// ---------------- K3: feats = enc @ w_tag^T + b_tag ----------------
#define FT_TOK 32
__global__ __launch_bounds__(256) void feats_kernel(const float* __restrict__ wtag,
                                                    const float* __restrict__ btag) {
    extern __shared__ float esm[];   // [FT_TOK][HIDC] = 64KB
    int warp = threadIdx.x >> 5, lane = threadIdx.x & 31;
    int tw = warp & 3, half = warp >> 2;
    float wreg[5][16];
#pragma unroll
    for (int t = 0; t < 5; t++)
#pragma unroll
        for (int q = 0; q < 16; q++)
            wreg[t][q] = wtag[(tw * 5 + t) * HIDC + q * 32 + lane];
    float bloc[5];
#pragma unroll
    for (int t = 0; t < 5; t++) bloc[t] = btag[tw * 5 + t];

    int tok0 = blockIdx.x * FT_TOK;
    const float4* src = (const float4*)(d_enc + (size_t)tok0 * HIDC);
    float4* dst = (float4*)esm;
    for (int i = threadIdx.x; i < FT_TOK * HIDC / 4; i += 256) dst[i] = src[i];
    __syncthreads();

    for (int tk = 0; tk < 16; tk++) {
        int tok = half * 16 + tk;
        float s[5] = {0.f, 0.f, 0.f, 0.f, 0.f};
#pragma unroll
        for (int q = 0; q < 16; q++) {
            float e = esm[tok * HIDC + q * 32 + lane];
#pragma unroll
            for (int t = 0; t < 5; t++) s[t] += e * wreg[t][q];
        }
#pragma unroll
        for (int t = 0; t < 5; t++) {
#pragma unroll
            for (int off = 16; off > 0; off >>= 1)
                s[t] += __shfl_xor_sync(0xffffffffu, s[t], off);
        }
        if (lane == 0) {
#pragma unroll
            for (int t = 0; t < 5; t++)
                d_feats[(tok0 + tok) * NTAG + tw * 5 + t] = s[t] + bloc[t];
        }
    }
}

// ---------------- V1: per-chunk maxplus products ----------------
__global__ __launch_bounds__(512) void viterbi_chunk_prod(const float* __restrict__ trans) {
    __shared__ float fsm[CLEN * NTAG];
    __shared__ float P[2][NTAG][NTAG];
    int c = blockIdx.x, tid = threadIdx.x;
    for (int i = tid; i < CLEN * NTAG; i += 512) fsm[i] = d_feats[c * CLEN * NTAG + i];
    __syncthreads();
    int j = tid / NTAG, k = tid % NTAG;
    bool act = (tid < NTAG * NTAG);
    float tr[NTAG];
    if (act) {
#pragma unroll
        for (int m = 0; m < NTAG; m++) tr[m] = trans[j * NTAG + m];
        P[0][j][k] = trans[j * NTAG + k] + fsm[j];
    }
    __syncthreads();
    int buf = 0;
    for (int t = 1; t < CLEN; t++) {
        if (act) {
            float v = -1e30f;
#pragma unroll
            for (int m = 0; m < NTAG; m++) v = fmaxf(v, tr[m] + P[buf][m][k]);
            P[buf ^ 1][j][k] = v + fsm[t * NTAG + j];
        }
        buf ^= 1;
        __syncthreads();
    }
    if (act) d_P[c * NTAG * NTAG + j * NTAG + k] = P[buf][j][k];
}

// ---------------- V2: sequential scan with prefetch ----------------
__global__ void viterbi_scan() {
    __shared__ float Ps[NTAG * NTAG];
    __shared__ float fvsm[NTAG];
    int lane = threadIdx.x;
    float cur[13], nx[13];
#pragma unroll
    for (int t = 0; t < 13; t++) {
        int i = lane + 32 * t;
        cur[t] = (i < NTAG * NTAG) ? d_P[i] : 0.f;
    }
    float fv = (lane == 18) ? 0.f : NEGV;
    for (int c = 0; c < NCHUNK; c++) {
#pragma unroll
        for (int t = 0; t < 13; t++) {
            int i = lane + 32 * t;
            if (i < NTAG * NTAG) Ps[i] = cur[t];
        }
        if (lane < NTAG) { d_fvs[c * NTAG + lane] = fv; fvsm[lane] = fv; }
        __syncwarp();
        if (c + 1 < NCHUNK) {
#pragma unroll
            for (int t = 0; t < 13; t++) {
                int i = lane + 32 * t;
                nx[t] = (i < NTAG * NTAG) ? d_P[(c + 1) * NTAG * NTAG + i] : 0.f;
            }
        }
        if (lane < NTAG) {
            float nf = -1e30f;
#pragma unroll
            for (int k = 0; k < NTAG; k++) nf = fmaxf(nf, Ps[lane * NTAG + k] + fvsm[k]);
            fv = nf;
        }
        __syncwarp();
#pragma unroll
        for (int t = 0; t < 13; t++) cur[t] = nx[t];
    }
}

// ---------------- V3: per-chunk forward + backpointers + chunk table (merged) ----------------
__global__ void viterbi_forward(const float* __restrict__ trans) {
    __shared__ float fsm[CLEN * NTAG];
    __shared__ unsigned char bsm[CLEN * NTAG];
    int c = blockIdx.x, lane = threadIdx.x;
    for (int i = lane; i < CLEN * NTAG; i += 32) fsm[i] = d_feats[c * CLEN * NTAG + i];
    __syncwarp();
    bool act = lane < NTAG;
    float tr[NTAG];
    if (act) {
#pragma unroll
        for (int m = 0; m < NTAG; m++) tr[m] = trans[lane * NTAG + m];
    }
    float fv = act ? d_fvs[c * NTAG + lane] : -1e30f;
    for (int t = 0; t < CLEN; t++) {
        float best = -1e30f;
        int bi = 0;
#pragma unroll
        for (int k = 0; k < NTAG; k++) {
            float v = __shfl_sync(0xffffffffu, fv, k);
            if (act) {
                v += tr[k];
                if (v > best) { best = v; bi = k; }
            }
        }
        if (act) {
            bsm[t * NTAG + lane] = (unsigned char)bi;
            fv = best + fsm[t * NTAG + lane];
        }
    }
    if (c == NCHUNK - 1 && act) d_finalfv[lane] = fv;
    __syncwarp();
    // bulk-write backpointers + compute chunk backtrack table
    uint4* dst = (uint4*)(d_bps + c * CLEN * NTAG);
    const uint4* srcv = (const uint4*)bsm;
    for (int i = lane; i < (CLEN * NTAG) / 16; i += 32) dst[i] = srcv[i];
    if (act) {
        int x = lane;
        for (int t = CLEN - 1; t >= 0; t--) x = bsm[t * NTAG + x];
        d_Wc[c * NTAG + lane] = (unsigned char)x;
    }
}

// ---------------- B2: terminal argmax + boundary scan ----------------
__global__ void terminal_and_scan(const float* __restrict__ trans, float* __restrict__ out) {
    __shared__ unsigned char Wsm[NCHUNK * NTAG];
    int lane = threadIdx.x;
    const uint4* src = (const uint4*)d_Wc;
    for (int i = lane; i < (NCHUNK * NTAG) / 16; i += 32) ((uint4*)Wsm)[i] = src[i];
    float term = (lane < NTAG) ? d_finalfv[lane] + trans[19 * NTAG + lane] : -1e30f;
    __syncwarp();
    float best = -1e30f;
    int bi = 0;
#pragma unroll
    for (int k = 0; k < NTAG; k++) {
        float v = __shfl_sync(0xffffffffu, term, k);
        if (v > best) { best = v; bi = k; }
    }
    if (lane == 0) {
        out[0] = best;
        int r = bi;
        d_r[NCHUNK - 1] = (unsigned char)r;
        for (int c = NCHUNK - 1; c >= 1; c--) {
            r = Wsm[c * NTAG + r];
            d_r[c - 1] = (unsigned char)r;
        }
    }
}

// ---------------- B3: path emission ----------------
__global__ void backtrack_emit(float* __restrict__ out) {
    __shared__ unsigned char b[CLEN * NTAG];
    int c = blockIdx.x, lane = threadIdx.x;
    const uint4* src = (const uint4*)(d_bps + c * CLEN * NTAG);
    uint4* dstv = (uint4*)b;
    for (int i = lane; i < (CLEN * NTAG) / 16; i += 32) dstv[i] = src[i];
    __syncwarp();
    if (lane == 0) {
        int x = d_r[c];
        float* o = out + 1 + c * CLEN;
        for (int t = CLEN - 1; t >= 0; t--) {
            o[t] = (float)x;
            x = b[t * NTAG + x];
        }
    }
}

// ---------------- launch ----------------
extern "C" void kernel_launch(void* const* d_in, const int* in_sizes, int n_in,
                              void* d_out, int out_size) {
    const float* x      = (const float*)d_in[0];
    const float* w_ih_f = (const float*)d_in[1];
    const float* b_ih_f = (const float*)d_in[3];
    const float* b_hh_f = (const float*)d_in[4];
    const float* w_ih_b = (const float*)d_in[5];
    const float* b_ih_b = (const float*)d_in[7];
    const float* b_hh_b = (const float*)d_in[8];
    const float* w_tag  = (const float*)d_in[9];
    const float* b_tag  = (const float*)d_in[10];
    const float* trans  = (const float*)d_in[11];
    float* out = (float*)d_out;

    cudaFuncSetAttribute(gemm_fused, cudaFuncAttributeMaxDynamicSharedMemorySize, GSMEM);
    cudaFuncSetAttribute(feats_kernel, cudaFuncAttributeMaxDynamicSharedMemorySize,
                         FT_TOK * HIDC * (int)sizeof(float));

    conv_x<<<(NTOK * HIN / 4) / 256, 256>>>(x);
    pack_w<<<(NPACK * HIN / 4) / 256, 256>>>(w_ih_f, w_ih_b, b_ih_f, b_hh_f, b_ih_b, b_hh_b);

    dim3 ggrid(NPACK / 192, NTOK / 128);
    gemm_fused<<<ggrid, 256, GSMEM>>>();

    feats_kernel<<<NTOK / FT_TOK, 256, FT_TOK * HIDC * sizeof(float)>>>(w_tag, b_tag);

    viterbi_chunk_prod<<<NCHUNK, 512>>>(trans);
    viterbi_scan<<<1, 32>>>();
    viterbi_forward<<<NCHUNK, 32>>>(trans);
    terminal_and_scan<<<1, 32>>>(trans, out);
    backtrack_emit<<<NCHUNK, 32>>>(out);
}

// round 8
// speedup vs baseline: 2.2600x; 1.0247x over previous
#include <cuda_runtime.h>
#include <cuda_bf16.h>
#include <cstdint>

// ---------------- problem constants ----------------
#define NTOK   16384
#define HIN    768
#define NPACK  1536      // grouped gate cols: 8 groups x 192 (= i|g|o x 64 j)
#define HIDC   512
#define NTAG   20
#define NCHUNK 128
#define CLEN   128
#define NEGV   (-10000.0f)

// ---------------- device scratch ----------------
__device__ __nv_bfloat16 d_Ahi[(size_t)NTOK * HIN];
__device__ __nv_bfloat16 d_Alo[(size_t)NTOK * HIN];
__device__ __nv_bfloat16 d_Bhi[(size_t)NPACK * HIN];   // grouped rows, K-major
__device__ __nv_bfloat16 d_Blo[(size_t)NPACK * HIN];
__device__ float d_biasG[NPACK];
__device__ float d_enc[(size_t)NTOK * HIDC];
__device__ float d_feats[NTOK * NTAG];
__device__ float d_P[NCHUNK * NTAG * NTAG];
__device__ float d_fvs[NCHUNK * NTAG];
__device__ float d_finalfv[NTAG];
__device__ unsigned char d_bps[NTOK * NTAG];
__device__ unsigned char d_Wc[NCHUNK * NTAG];
__device__ unsigned char d_r[NCHUNK];

// ---------------- helpers ----------------
__device__ __forceinline__ uint32_t smem_u32(const void* p) {
    uint32_t a;
    asm("{ .reg .u64 t; cvta.to.shared.u64 t, %1; cvt.u32.u64 %0, t; }" : "=r"(a) : "l"(p));
    return a;
}
#define CP_ASYNC16(dst, src) \
    asm volatile("cp.async.cg.shared.global [%0], [%1], 16;" :: "r"(dst), "l"(src))
#define CP_COMMIT() asm volatile("cp.async.commit_group;" ::: "memory")
#define CP_WAIT(n)  asm volatile("cp.async.wait_group %0;" :: "n"(n) : "memory")

__device__ __forceinline__ void ldm_x4(uint32_t* r, uint32_t addr) {
    asm volatile("ldmatrix.sync.aligned.m8n8.x4.shared.b16 {%0,%1,%2,%3}, [%4];"
                 : "=r"(r[0]), "=r"(r[1]), "=r"(r[2]), "=r"(r[3]) : "r"(addr));
}
__device__ __forceinline__ void mma16816(float* c, const uint32_t* a, uint32_t b0, uint32_t b1) {
    asm volatile(
        "mma.sync.aligned.m16n8k16.row.col.f32.bf16.bf16.f32 "
        "{%0,%1,%2,%3}, {%4,%5,%6,%7}, {%8,%9}, {%0,%1,%2,%3};"
        : "+f"(c[0]), "+f"(c[1]), "+f"(c[2]), "+f"(c[3])
        : "r"(a[0]), "r"(a[1]), "r"(a[2]), "r"(a[3]), "r"(b0), "r"(b1));
}
__device__ __forceinline__ void split2(float f, __nv_bfloat16& h, __nv_bfloat16& l) {
    h = __float2bfloat16_rn(f);
    l = __float2bfloat16_rn(f - __bfloat162float(h));
}

// ---------------- K0: merged input split + weight pack ----------------
#define XBLK ((NTOK * HIN / 4) / 256)     // 12288
#define WBLK ((NPACK * HIN / 4) / 256)    // 1152
__global__ void prep_kernel(const float* __restrict__ x,
                            const float* __restrict__ wf, const float* __restrict__ wb,
                            const float* __restrict__ bihf, const float* __restrict__ bhhf,
                            const float* __restrict__ bihb, const float* __restrict__ bhhb) {
    int b = blockIdx.x;
    if (b < XBLK) {
        int idx = b * 256 + threadIdx.x;
        float4 v = *(const float4*)(x + HIN + (size_t)idx * 4);  // skip token 0
        float f[4] = {v.x, v.y, v.z, v.w};
        __nv_bfloat16 hi[4], lo[4];
#pragma unroll
        for (int i = 0; i < 4; i++) split2(f[i], hi[i], lo[i]);
        *(ulonglong1*)(d_Ahi + (size_t)idx * 4) = *(ulonglong1*)hi;
        *(ulonglong1*)(d_Alo + (size_t)idx * 4) = *(ulonglong1*)lo;
    } else {
        int idx = (b - XBLK) * 256 + threadIdx.x;
        int n = idx / (HIN / 4);
        int kq = (idx % (HIN / 4)) * 4;
        int g = n / 192, cg = n % 192;
        int dir = g >> 2, jblk = g & 3;
        int gate = cg / 64, jj = cg % 64;
        int gateoff = (gate == 0) ? 0 : (gate == 1 ? 512 : 768);
        int r = gateoff + jblk * 64 + jj;
        const float* w = dir ? wb : wf;
        float4 v = *(const float4*)(w + (size_t)r * HIN + kq);
        float f[4] = {v.x, v.y, v.z, v.w};
        __nv_bfloat16 hi[4], lo[4];
#pragma unroll
        for (int i = 0; i < 4; i++) split2(f[i], hi[i], lo[i]);
        *(ulonglong1*)(d_Bhi + (size_t)n * HIN + kq) = *(ulonglong1*)hi;
        *(ulonglong1*)(d_Blo + (size_t)n * HIN + kq) = *(ulonglong1*)lo;
        if (kq == 0) {
            const float* bih = dir ? bihb : bihf;
            const float* bhh = dir ? bhhb : bhhf;
            d_biasG[n] = bih[r] + bhh[r];
        }
    }
}

// ---------------- K1: fused bf16 mma GEMM (3-term split) + LSTM activation ----------------
// 512 threads, 16 warps, warp tile 32x48
#define BKE 32
#define ASTR 40
#define NKI 72                    // 3 passes x 24 k-tiles of 32 over K=768
#define SA_STAGE (128 * ASTR)
#define SB_STAGE (192 * ASTR)
#define GSMEM ((4 * SA_STAGE + 4 * SB_STAGE) * 2)   // 102400 B
#define EXSTR 196

// phase q = kt/24: 0:(Ahi,Bhi) 1:(Ahi,Blo) 2:(Alo,Bhi); offset (kt%24)*32
#define KSRC(kt, pa, pb)                                                        \
    do {                                                                        \
        int q_ = (kt) / 24, off_ = ((kt) % 24) * BKE;                           \
        pa = (q_ == 2 ? d_Alo : d_Ahi) + (size_t)(bm * 128) * HIN + off_;       \
        pb = (q_ == 1 ? d_Blo : d_Bhi) + (size_t)(g * 192) * HIN + off_;        \
    } while (0)

__global__ __launch_bounds__(512, 1) void gemm_fused() {
    extern __shared__ char dsm[];
    __nv_bfloat16* Asm = (__nv_bfloat16*)dsm;
    __nv_bfloat16* Bsm = Asm + 4 * SA_STAGE;
    float* Ex = (float*)dsm;                 // epilogue overlay: 64 x EXSTR fp32
    int tid = threadIdx.x;
    int wid = tid >> 5, lane = tid & 31;
    int wm = wid >> 2, wn = wid & 3;         // warp tile 32 x 48 (wm: 0..3)
    int g = blockIdx.x, bm = blockIdx.y;

    uint32_t sA = smem_u32(Asm), sB = smem_u32(Bsm);

    float acc[2][6][4];
#pragma unroll
    for (int i = 0; i < 2; i++)
#pragma unroll
        for (int j = 0; j < 6; j++)
#pragma unroll
            for (int q = 0; q < 4; q++) acc[i][j][q] = 0.f;

#define LOAD_STAGE(s, pa, pb)                                                            \
    do {                                                                                 \
        {                                                                                \
            int c_ = tid;                                                                \
            int row_ = c_ >> 2, seg_ = c_ & 3;                                           \
            CP_ASYNC16(sA + (uint32_t)(((s) * SA_STAGE + row_ * ASTR + seg_ * 8) * 2),   \
                       (pa) + (size_t)row_ * HIN + seg_ * 8);                            \
        }                                                                                \
        _Pragma("unroll")                                                                \
        for (int i_ = 0; i_ < 2; i_++) {                                                 \
            int c_ = tid + i_ * 512;                                                     \
            if (c_ < 768) {                                                              \
                int row_ = c_ >> 2, seg_ = c_ & 3;                                       \
                CP_ASYNC16(sB + (uint32_t)(((s) * SB_STAGE + row_ * ASTR + seg_ * 8) * 2), \
                           (pb) + (size_t)row_ * HIN + seg_ * 8);                        \
            }                                                                            \
        }                                                                                \
    } while (0)

    {
        const __nv_bfloat16 *pa, *pb;
        KSRC(0, pa, pb); LOAD_STAGE(0, pa, pb); CP_COMMIT();
        KSRC(1, pa, pb); LOAD_STAGE(1, pa, pb); CP_COMMIT();
        KSRC(2, pa, pb); LOAD_STAGE(2, pa, pb); CP_COMMIT();
    }

    for (int kt = 0; kt < NKI; kt++) {
        if (kt < NKI - 2) { CP_WAIT(2); }
        else if (kt == NKI - 2) { CP_WAIT(1); }
        else { CP_WAIT(0); }
        __syncthreads();
        int cs = kt & 3;

#pragma unroll
        for (int ks = 0; ks < 2; ks++) {
            int k0 = ks * 16;
            uint32_t afr[2][4];
#pragma unroll
            for (int i = 0; i < 2; i++) {
                int row = wm * 32 + i * 16 + (lane & 15);
                uint32_t addr = sA + (uint32_t)((cs * SA_STAGE + row * ASTR + k0 + ((lane >> 4) * 8)) * 2);
                ldm_x4(afr[i], addr);
            }
            uint32_t bfr[3][4];
#pragma unroll
            for (int p = 0; p < 3; p++) {
                int row = wn * 48 + p * 16 + (lane & 15);
                uint32_t addr = sB + (uint32_t)((cs * SB_STAGE + row * ASTR + k0 + ((lane >> 4) * 8)) * 2);
                ldm_x4(bfr[p], addr);
            }
#pragma unroll
            for (int i = 0; i < 2; i++)
#pragma unroll
                for (int p = 0; p < 3; p++) {
                    mma16816(acc[i][2 * p + 0], afr[i], bfr[p][0], bfr[p][2]);
                    mma16816(acc[i][2 * p + 1], afr[i], bfr[p][1], bfr[p][3]);
                }
        }

        if (kt + 3 < NKI) {
            const __nv_bfloat16 *pa, *pb;
            KSRC(kt + 3, pa, pb);
            LOAD_STAGE((kt + 3) & 3, pa, pb);
            CP_COMMIT();
        }
    }
    __syncthreads();

    // ---- fused epilogue: bias + LSTM activation -> enc ----
    float2 bias[6];
#pragma unroll
    for (int jt = 0; jt < 6; jt++) {
        int col = g * 192 + wn * 48 + jt * 8 + (lane & 3) * 2;
        bias[jt] = *(const float2*)(d_biasG + col);
    }
    int dir = g >> 2, jblk = g & 3;
    int base = dir * 256 + jblk * 64;

#pragma unroll
    for (int ch = 0; ch < 2; ch++) {
        if ((wm >> 1) == ch) {
#pragma unroll
            for (int i = 0; i < 2; i++) {
                int r = (wm & 1) * 32 + i * 16 + (lane >> 2);
                int cbase = wn * 48 + (lane & 3) * 2;
#pragma unroll
                for (int jt = 0; jt < 6; jt++) {
                    int c = cbase + jt * 8;
                    Ex[r * EXSTR + c]           = acc[i][jt][0] + bias[jt].x;
                    Ex[r * EXSTR + c + 1]       = acc[i][jt][1] + bias[jt].y;
                    Ex[(r + 8) * EXSTR + c]     = acc[i][jt][2] + bias[jt].x;
                    Ex[(r + 8) * EXSTR + c + 1] = acc[i][jt][3] + bias[jt].y;
                }
            }
        }
        __syncthreads();
#pragma unroll
        for (int u = 0; u < 8; u++) {
            int idx = u * 512 + tid;
            int r = idx >> 6, j = idx & 63;
            float iv = Ex[r * EXSTR + j];
            float gv = Ex[r * EXSTR + 64 + j];
            float ov = Ex[r * EXSTR + 128 + j];
            float si = 1.f / (1.f + expf(-iv));
            float cc = si * tanhf(gv);
            float so = 1.f / (1.f + expf(-ov));
            d_enc[(size_t)(bm * 128 + ch * 64 + r) * HIDC + base + j] = so * tanhf(cc);
        }
        __syncthreads();
    }
}

// ---------------- K3: feats = enc @ w_tag^T + b_tag ----------------
#define FT_TOK 32
__global__ __launch_bounds__(256) void feats_kernel(const float* __restrict__ wtag,
                                                    const float* __restrict__ btag) {
    extern __shared__ float esm[];   // [FT_TOK][HIDC] = 64KB
    int warp = threadIdx.x >> 5, lane = threadIdx.x & 31;
    int tw = warp & 3, half = warp >> 2;
    float wreg[5][16];
#pragma unroll
    for (int t = 0; t < 5; t++)
#pragma unroll
        for (int q = 0; q < 16; q++)
            wreg[t][q] = wtag[(tw * 5 + t) * HIDC + q * 32 + lane];
    float bloc[5];
#pragma unroll
    for (int t = 0; t < 5; t++) bloc[t] = btag[tw * 5 + t];

    int tok0 = blockIdx.x * FT_TOK;
    const float4* src = (const float4*)(d_enc + (size_t)tok0 * HIDC);
    float4* dst = (float4*)esm;
    for (int i = threadIdx.x; i < FT_TOK * HIDC / 4; i += 256) dst[i] = src[i];
    __syncthreads();

    for (int tk = 0; tk < 16; tk++) {
        int tok = half * 16 + tk;
        float s[5] = {0.f, 0.f, 0.f, 0.f, 0.f};
#pragma unroll
        for (int q = 0; q < 16; q++) {
            float e = esm[tok * HIDC + q * 32 + lane];
#pragma unroll
            for (int t = 0; t < 5; t++) s[t] += e * wreg[t][q];
        }
#pragma unroll
        for (int t = 0; t < 5; t++) {
#pragma unroll
            for (int off = 16; off > 0; off >>= 1)
                s[t] += __shfl_xor_sync(0xffffffffu, s[t], off);
        }
        if (lane == 0) {
#pragma unroll
            for (int t = 0; t < 5; t++)
                d_feats[(tok0 + tok) * NTAG + tw * 5 + t] = s[t] + bloc[t];
        }
    }
}

// ---------------- V1: per-chunk maxplus products ----------------
__global__ __launch_bounds__(512) void viterbi_chunk_prod(const float* __restrict__ trans) {
    __shared__ float fsm[CLEN * NTAG];
    __shared__ float P[2][NTAG][NTAG];
    int c = blockIdx.x, tid = threadIdx.x;
    for (int i = tid; i < CLEN * NTAG; i += 512) fsm[i] = d_feats[c * CLEN * NTAG + i];
    __syncthreads();
    int j = tid / NTAG, k = tid % NTAG;
    bool act = (tid < NTAG * NTAG);
    float tr[NTAG];
    if (act) {
#pragma unroll
        for (int m = 0; m < NTAG; m++) tr[m] = trans[j * NTAG + m];
        P[0][j][k] = trans[j * NTAG + k] + fsm[j];
    }
    __syncthreads();
    int buf = 0;
    for (int t = 1; t < CLEN; t++) {
        if (act) {
            float v = -1e30f;
#pragma unroll
            for (int m = 0; m < NTAG; m++) v = fmaxf(v, tr[m] + P[buf][m][k]);
            P[buf ^ 1][j][k] = v + fsm[t * NTAG + j];
        }
        buf ^= 1;
        __syncthreads();
    }
    if (act) d_P[c * NTAG * NTAG + j * NTAG + k] = P[buf][j][k];
}

// ---------------- V2: sequential scan with prefetch ----------------
__global__ void viterbi_scan() {
    __shared__ float Ps[NTAG * NTAG];
    __shared__ float fvsm[NTAG];
    int lane = threadIdx.x;
    float cur[13], nx[13];
#pragma unroll
    for (int t = 0; t < 13; t++) {
        int i = lane + 32 * t;
        cur[t] = (i < NTAG * NTAG) ? d_P[i] : 0.f;
    }
    float fv = (lane == 18) ? 0.f : NEGV;
    for (int c = 0; c < NCHUNK; c++) {
#pragma unroll
        for (int t = 0; t < 13; t++) {
            int i = lane + 32 * t;
            if (i < NTAG * NTAG) Ps[i] = cur[t];
        }
        if (lane < NTAG) { d_fvs[c * NTAG + lane] = fv; fvsm[lane] = fv; }
        __syncwarp();
        if (c + 1 < NCHUNK) {
#pragma unroll
            for (int t = 0; t < 13; t++) {
                int i = lane + 32 * t;
                nx[t] = (i < NTAG * NTAG) ? d_P[(c + 1) * NTAG * NTAG + i] : 0.f;
            }
        }
        if (lane < NTAG) {
            float nf = -1e30f;
#pragma unroll
            for (int k = 0; k < NTAG; k++) nf = fmaxf(nf, Ps[lane * NTAG + k] + fvsm[k]);
            fv = nf;
        }
        __syncwarp();
#pragma unroll
        for (int t = 0; t < 13; t++) cur[t] = nx[t];
    }
}

// ---------------- V3: per-chunk forward + backpointers + chunk table (merged) ----------------
__global__ void viterbi_forward(const float* __restrict__ trans) {
    __shared__ float fsm[CLEN * NTAG];
    __shared__ unsigned char bsm[CLEN * NTAG];
    int c = blockIdx.x, lane = threadIdx.x;
    for (int i = lane; i < CLEN * NTAG; i += 32) fsm[i] = d_feats[c * CLEN * NTAG + i];
    __syncwarp();
    bool act = lane < NTAG;
    float tr[NTAG];
    if (act) {
#pragma unroll
        for (int m = 0; m < NTAG; m++) tr[m] = trans[lane * NTAG + m];
    }
    float fv = act ? d_fvs[c * NTAG + lane] : -1e30f;
    for (int t = 0; t < CLEN; t++) {
        float best = -1e30f;
        int bi = 0;
#pragma unroll
        for (int k = 0; k < NTAG; k++) {
            float v = __shfl_sync(0xffffffffu, fv, k);
            if (act) {
                v += tr[k];
                if (v > best) { best = v; bi = k; }
            }
        }
        if (act) {
            bsm[t * NTAG + lane] = (unsigned char)bi;
            fv = best + fsm[t * NTAG + lane];
        }
    }
    if (c == NCHUNK - 1 && act) d_finalfv[lane] = fv;
    __syncwarp();
    uint4* dst = (uint4*)(d_bps + c * CLEN * NTAG);
    const uint4* srcv = (const uint4*)bsm;
    for (int i = lane; i < (CLEN * NTAG) / 16; i += 32) dst[i] = srcv[i];
    if (act) {
        int x = lane;
        for (int t = CLEN - 1; t >= 0; t--) x = bsm[t * NTAG + x];
        d_Wc[c * NTAG + lane] = (unsigned char)x;
    }
}

// ---------------- B2: terminal argmax + boundary scan ----------------
__global__ void terminal_and_scan(const float* __restrict__ trans, float* __restrict__ out) {
    __shared__ unsigned char Wsm[NCHUNK * NTAG];
    int lane = threadIdx.x;
    const uint4* src = (const uint4*)d_Wc;
    for (int i = lane; i < (NCHUNK * NTAG) / 16; i += 32) ((uint4*)Wsm)[i] = src[i];
    float term = (lane < NTAG) ? d_finalfv[lane] + trans[19 * NTAG + lane] : -1e30f;
    __syncwarp();
    float best = -1e30f;
    int bi = 0;
#pragma unroll
    for (int k = 0; k < NTAG; k++) {
        float v = __shfl_sync(0xffffffffu, term, k);
        if (v > best) { best = v; bi = k; }
    }
    if (lane == 0) {
        out[0] = best;
        int r = bi;
        d_r[NCHUNK - 1] = (unsigned char)r;
        for (int c = NCHUNK - 1; c >= 1; c--) {
            r = Wsm[c * NTAG + r];
            d_r[c - 1] = (unsigned char)r;
        }
    }
}

// ---------------- B3: path emission ----------------
__global__ void backtrack_emit(float* __restrict__ out) {
    __shared__ unsigned char b[CLEN * NTAG];
    int c = blockIdx.x, lane = threadIdx.x;
    const uint4* src = (const uint4*)(d_bps + c * CLEN * NTAG);
    uint4* dstv = (uint4*)b;
    for (int i = lane; i < (CLEN * NTAG) / 16; i += 32) dstv[i] = src[i];
    __syncwarp();
    if (lane == 0) {
        int x = d_r[c];
        float* o = out + 1 + c * CLEN;
        for (int t = CLEN - 1; t >= 0; t--) {
            o[t] = (float)x;
            x = b[t * NTAG + x];
        }
    }
}

// ---------------- launch ----------------
extern "C" void kernel_launch(void* const* d_in, const int* in_sizes, int n_in,
                              void* d_out, int out_size) {
    const float* x      = (const float*)d_in[0];
    const float* w_ih_f = (const float*)d_in[1];
    const float* b_ih_f = (const float*)d_in[3];
    const float* b_hh_f = (const float*)d_in[4];
    const float* w_ih_b = (const float*)d_in[5];
    const float* b_ih_b = (const float*)d_in[7];
    const float* b_hh_b = (const float*)d_in[8];
    const float* w_tag  = (const float*)d_in[9];
    const float* b_tag  = (const float*)d_in[10];
    const float* trans  = (const float*)d_in[11];
    float* out = (float*)d_out;

    cudaFuncSetAttribute(gemm_fused, cudaFuncAttributeMaxDynamicSharedMemorySize, GSMEM);
    cudaFuncSetAttribute(feats_kernel, cudaFuncAttributeMaxDynamicSharedMemorySize,
                         FT_TOK * HIDC * (int)sizeof(float));

    prep_kernel<<<XBLK + WBLK, 256>>>(x, w_ih_f, w_ih_b, b_ih_f, b_hh_f, b_ih_b, b_hh_b);

    dim3 ggrid(NPACK / 192, NTOK / 128);
    gemm_fused<<<ggrid, 512, GSMEM>>>();

    feats_kernel<<<NTOK / FT_TOK, 256, FT_TOK * HIDC * sizeof(float)>>>(w_tag, b_tag);

    viterbi_chunk_prod<<<NCHUNK, 512>>>(trans);
    viterbi_scan<<<1, 32>>>();
    viterbi_forward<<<NCHUNK, 32>>>(trans);
    terminal_and_scan<<<1, 32>>>(trans, out);
    backtrack_emit<<<NCHUNK, 32>>>(out);
}

// round 9
// speedup vs baseline: 2.4323x; 1.0762x over previous
#include <cuda_runtime.h>
#include <cuda_bf16.h>
#include <cstdint>

// ---------------- problem constants ----------------
#define NTOK   16384
#define HIN    768
#define NPACK  1536      // grouped gate cols: 16 groups x 96 (= i|g|o x 32 j)
#define HIDC   512
#define NTAG   20
#define NCHUNK 128
#define CLEN   128
#define NEGV   (-10000.0f)

// ---------------- device scratch ----------------
__device__ __nv_bfloat16 d_Ahi[(size_t)NTOK * HIN];
__device__ __nv_bfloat16 d_Alo[(size_t)NTOK * HIN];
__device__ __nv_bfloat16 d_Bhi[(size_t)NPACK * HIN];   // grouped rows, K-major
__device__ __nv_bfloat16 d_Blo[(size_t)NPACK * HIN];
__device__ float d_biasG[NPACK];
__device__ float d_enc[(size_t)NTOK * HIDC];
__device__ float d_feats[NTOK * NTAG];
__device__ float d_P[NCHUNK * NTAG * NTAG];
__device__ float d_fvs[NCHUNK * NTAG];
__device__ float d_finalfv[NTAG];
__device__ unsigned char d_bps[NTOK * NTAG];
__device__ unsigned char d_Wc[NCHUNK * NTAG];
__device__ unsigned char d_r[NCHUNK];

// ---------------- helpers ----------------
__device__ __forceinline__ uint32_t smem_u32(const void* p) {
    uint32_t a;
    asm("{ .reg .u64 t; cvta.to.shared.u64 t, %1; cvt.u32.u64 %0, t; }" : "=r"(a) : "l"(p));
    return a;
}
#define CP_ASYNC16(dst, src) \
    asm volatile("cp.async.cg.shared.global [%0], [%1], 16;" :: "r"(dst), "l"(src))
#define CP_COMMIT() asm volatile("cp.async.commit_group;" ::: "memory")
#define CP_WAIT(n)  asm volatile("cp.async.wait_group %0;" :: "n"(n) : "memory")

__device__ __forceinline__ void ldm_x4(uint32_t* r, uint32_t addr) {
    asm volatile("ldmatrix.sync.aligned.m8n8.x4.shared.b16 {%0,%1,%2,%3}, [%4];"
                 : "=r"(r[0]), "=r"(r[1]), "=r"(r[2]), "=r"(r[3]) : "r"(addr));
}
__device__ __forceinline__ void mma16816(float* c, const uint32_t* a, uint32_t b0, uint32_t b1) {
    asm volatile(
        "mma.sync.aligned.m16n8k16.row.col.f32.bf16.bf16.f32 "
        "{%0,%1,%2,%3}, {%4,%5,%6,%7}, {%8,%9}, {%0,%1,%2,%3};"
        : "+f"(c[0]), "+f"(c[1]), "+f"(c[2]), "+f"(c[3])
        : "r"(a[0]), "r"(a[1]), "r"(a[2]), "r"(a[3]), "r"(b0), "r"(b1));
}
__device__ __forceinline__ void split2(float f, __nv_bfloat16& h, __nv_bfloat16& l) {
    h = __float2bfloat16_rn(f);
    l = __float2bfloat16_rn(f - __bfloat162float(h));
}

// ---------------- K0: merged input split + weight pack ----------------
// grouped row n: g = n/96 (dir=g>>3, jblk=g&7), cg=n%96, gate=cg/32, jj=cg%32
#define XBLK ((NTOK * HIN / 4) / 256)     // 12288
#define WBLK ((NPACK * HIN / 4) / 256)    // 1152
__global__ void prep_kernel(const float* __restrict__ x,
                            const float* __restrict__ wf, const float* __restrict__ wb,
                            const float* __restrict__ bihf, const float* __restrict__ bhhf,
                            const float* __restrict__ bihb, const float* __restrict__ bhhb) {
    int b = blockIdx.x;
    if (b < XBLK) {
        int idx = b * 256 + threadIdx.x;
        float4 v = *(const float4*)(x + HIN + (size_t)idx * 4);  // skip token 0
        float f[4] = {v.x, v.y, v.z, v.w};
        __nv_bfloat16 hi[4], lo[4];
#pragma unroll
        for (int i = 0; i < 4; i++) split2(f[i], hi[i], lo[i]);
        *(ulonglong1*)(d_Ahi + (size_t)idx * 4) = *(ulonglong1*)hi;
        *(ulonglong1*)(d_Alo + (size_t)idx * 4) = *(ulonglong1*)lo;
    } else {
        int idx = (b - XBLK) * 256 + threadIdx.x;
        int n = idx / (HIN / 4);
        int kq = (idx % (HIN / 4)) * 4;
        int g = n / 96, cg = n % 96;
        int dir = g >> 3, jblk = g & 7;
        int gate = cg / 32, jj = cg % 32;
        int gateoff = (gate == 0) ? 0 : (gate == 1 ? 512 : 768);
        int r = gateoff + jblk * 32 + jj;
        const float* w = dir ? wb : wf;
        float4 v = *(const float4*)(w + (size_t)r * HIN + kq);
        float f[4] = {v.x, v.y, v.z, v.w};
        __nv_bfloat16 hi[4], lo[4];
#pragma unroll
        for (int i = 0; i < 4; i++) split2(f[i], hi[i], lo[i]);
        *(ulonglong1*)(d_Bhi + (size_t)n * HIN + kq) = *(ulonglong1*)hi;
        *(ulonglong1*)(d_Blo + (size_t)n * HIN + kq) = *(ulonglong1*)lo;
        if (kq == 0) {
            const float* bih = dir ? bihb : bihf;
            const float* bhh = dir ? bhhb : bhhf;
            d_biasG[n] = bih[r] + bhh[r];
        }
    }
}

// ---------------- K1: fused bf16 mma GEMM (3-term split) + LSTM activation ----------------
// CTA tile 128x96, 256 threads, 8 warps (warp tile 32x48), 2 CTAs/SM
#define BKE 32
#define ASTR 40
#define NKI 72                    // 3 passes x 24 k-tiles of 32 over K=768
#define SA_STAGE (128 * ASTR)
#define SB_STAGE (96 * ASTR)
#define GSMEM ((4 * SA_STAGE + 4 * SB_STAGE) * 2)   // 71680 B
#define EXSTR 100

// phase q = kt/24: 0:(Ahi,Bhi) 1:(Ahi,Blo) 2:(Alo,Bhi); offset (kt%24)*32
#define KSRC(kt, pa, pb)                                                        \
    do {                                                                        \
        int q_ = (kt) / 24, off_ = ((kt) % 24) * BKE;                           \
        pa = (q_ == 2 ? d_Alo : d_Ahi) + (size_t)(bm * 128) * HIN + off_;       \
        pb = (q_ == 1 ? d_Blo : d_Bhi) + (size_t)(g * 96) * HIN + off_;         \
    } while (0)

__global__ __launch_bounds__(256, 2) void gemm_fused() {
    extern __shared__ char dsm[];
    __nv_bfloat16* Asm = (__nv_bfloat16*)dsm;
    __nv_bfloat16* Bsm = Asm + 4 * SA_STAGE;
    float* Ex = (float*)dsm;                 // epilogue overlay: 64 x EXSTR fp32
    int tid = threadIdx.x;
    int wid = tid >> 5, lane = tid & 31;
    int wm = wid >> 1, wn = wid & 1;         // warp tile 32 x 48 (wm 0..3, wn 0..1)
    int g = blockIdx.x, bm = blockIdx.y;

    uint32_t sA = smem_u32(Asm), sB = smem_u32(Bsm);

    float acc[2][6][4];
#pragma unroll
    for (int i = 0; i < 2; i++)
#pragma unroll
        for (int j = 0; j < 6; j++)
#pragma unroll
            for (int q = 0; q < 4; q++) acc[i][j][q] = 0.f;

#define LOAD_STAGE(s, pa, pb)                                                            \
    do {                                                                                 \
        _Pragma("unroll")                                                                \
        for (int i_ = 0; i_ < 2; i_++) {                                                 \
            int c_ = tid + i_ * 256;                                                     \
            int row_ = c_ >> 2, seg_ = c_ & 3;                                           \
            CP_ASYNC16(sA + (uint32_t)(((s) * SA_STAGE + row_ * ASTR + seg_ * 8) * 2),   \
                       (pa) + (size_t)row_ * HIN + seg_ * 8);                            \
        }                                                                                \
        _Pragma("unroll")                                                                \
        for (int i_ = 0; i_ < 2; i_++) {                                                 \
            int c_ = tid + i_ * 256;                                                     \
            if (c_ < 384) {                                                              \
                int row_ = c_ >> 2, seg_ = c_ & 3;                                       \
                CP_ASYNC16(sB + (uint32_t)(((s) * SB_STAGE + row_ * ASTR + seg_ * 8) * 2), \
                           (pb) + (size_t)row_ * HIN + seg_ * 8);                        \
            }                                                                            \
        }                                                                                \
    } while (0)

    {
        const __nv_bfloat16 *pa, *pb;
        KSRC(0, pa, pb); LOAD_STAGE(0, pa, pb); CP_COMMIT();
        KSRC(1, pa, pb); LOAD_STAGE(1, pa, pb); CP_COMMIT();
        KSRC(2, pa, pb); LOAD_STAGE(2, pa, pb); CP_COMMIT();
    }

    for (int kt = 0; kt < NKI; kt++) {
        if (kt < NKI - 2) { CP_WAIT(2); }
        else if (kt == NKI - 2) { CP_WAIT(1); }
        else { CP_WAIT(0); }
        __syncthreads();
        int cs = kt & 3;

#pragma unroll
        for (int ks = 0; ks < 2; ks++) {
            int k0 = ks * 16;
            uint32_t afr[2][4];
#pragma unroll
            for (int i = 0; i < 2; i++) {
                int row = wm * 32 + i * 16 + (lane & 15);
                uint32_t addr = sA + (uint32_t)((cs * SA_STAGE + row * ASTR + k0 + ((lane >> 4) * 8)) * 2);
                ldm_x4(afr[i], addr);
            }
            uint32_t bfr[3][4];
#pragma unroll
            for (int p = 0; p < 3; p++) {
                int row = wn * 48 + p * 16 + (lane & 15);
                uint32_t addr = sB + (uint32_t)((cs * SB_STAGE + row * ASTR + k0 + ((lane >> 4) * 8)) * 2);
                ldm_x4(bfr[p], addr);
            }
#pragma unroll
            for (int i = 0; i < 2; i++)
#pragma unroll
                for (int p = 0; p < 3; p++) {
                    mma16816(acc[i][2 * p + 0], afr[i], bfr[p][0], bfr[p][2]);
                    mma16816(acc[i][2 * p + 1], afr[i], bfr[p][1], bfr[p][3]);
                }
        }

        if (kt + 3 < NKI) {
            const __nv_bfloat16 *pa, *pb;
            KSRC(kt + 3, pa, pb);
            LOAD_STAGE((kt + 3) & 3, pa, pb);
            CP_COMMIT();
        }
    }
    __syncthreads();

    // ---- fused epilogue: bias + LSTM activation -> enc ----
    float2 bias[6];
#pragma unroll
    for (int jt = 0; jt < 6; jt++) {
        int col = g * 96 + wn * 48 + jt * 8 + (lane & 3) * 2;
        bias[jt] = *(const float2*)(d_biasG + col);
    }
    int dir = g >> 3, jblk = g & 7;
    int base = dir * 256 + jblk * 32;

#pragma unroll
    for (int ch = 0; ch < 2; ch++) {
        if ((wm >> 1) == ch) {
#pragma unroll
            for (int i = 0; i < 2; i++) {
                int r = (wm & 1) * 32 + i * 16 + (lane >> 2);
                int cbase = wn * 48 + (lane & 3) * 2;
#pragma unroll
                for (int jt = 0; jt < 6; jt++) {
                    int c = cbase + jt * 8;
                    Ex[r * EXSTR + c]           = acc[i][jt][0] + bias[jt].x;
                    Ex[r * EXSTR + c + 1]       = acc[i][jt][1] + bias[jt].y;
                    Ex[(r + 8) * EXSTR + c]     = acc[i][jt][2] + bias[jt].x;
                    Ex[(r + 8) * EXSTR + c + 1] = acc[i][jt][3] + bias[jt].y;
                }
            }
        }
        __syncthreads();
        // 64 rows x 32 j outputs = 2048 -> 8 iters of 256 threads
#pragma unroll
        for (int u = 0; u < 8; u++) {
            int idx = u * 256 + tid;
            int r = idx >> 5, j = idx & 31;
            float iv = Ex[r * EXSTR + j];
            float gv = Ex[r * EXSTR + 32 + j];
            float ov = Ex[r * EXSTR + 64 + j];
            float si = 1.f / (1.f + expf(-iv));
            float cc = si * tanhf(gv);
            float so = 1.f / (1.f + expf(-ov));
            d_enc[(size_t)(bm * 128 + ch * 64 + r) * HIDC + base + j] = so * tanhf(cc);
        }
        __syncthreads();
    }
}

// ---------------- K3: feats = enc @ w_tag^T + b_tag ----------------
#define FT_TOK 32
__global__ __launch_bounds__(256) void feats_kernel(const float* __restrict__ wtag,
                                                    const float* __restrict__ btag) {
    extern __shared__ float esm[];   // [FT_TOK][HIDC] = 64KB
    int warp = threadIdx.x >> 5, lane = threadIdx.x & 31;
    int tw = warp & 3, half = warp >> 2;
    float wreg[5][16];
#pragma unroll
    for (int t = 0; t < 5; t++)
#pragma unroll
        for (int q = 0; q < 16; q++)
            wreg[t][q] = wtag[(tw * 5 + t) * HIDC + q * 32 + lane];
    float bloc[5];
#pragma unroll
    for (int t = 0; t < 5; t++) bloc[t] = btag[tw * 5 + t];

    int tok0 = blockIdx.x * FT_TOK;
    const float4* src = (const float4*)(d_enc + (size_t)tok0 * HIDC);
    float4* dst = (float4*)esm;
    for (int i = threadIdx.x; i < FT_TOK * HIDC / 4; i += 256) dst[i] = src[i];
    __syncthreads();

    // two tokens in flight -> interleaved shfl chains
    for (int tk = 0; tk < 8; tk++) {
        int tokA = half * 16 + tk;
        int tokB = tokA + 8;
        float sA[5] = {0.f, 0.f, 0.f, 0.f, 0.f};
        float sB[5] = {0.f, 0.f, 0.f, 0.f, 0.f};
#pragma unroll
        for (int q = 0; q < 16; q++) {
            float eA = esm[tokA * HIDC + q * 32 + lane];
            float eB = esm[tokB * HIDC + q * 32 + lane];
#pragma unroll
            for (int t = 0; t < 5; t++) {
                sA[t] += eA * wreg[t][q];
                sB[t] += eB * wreg[t][q];
            }
        }
#pragma unroll
        for (int t = 0; t < 5; t++) {
#pragma unroll
            for (int off = 16; off > 0; off >>= 1) {
                sA[t] += __shfl_xor_sync(0xffffffffu, sA[t], off);
                sB[t] += __shfl_xor_sync(0xffffffffu, sB[t], off);
            }
        }
        if (lane == 0) {
#pragma unroll
            for (int t = 0; t < 5; t++) {
                d_feats[(tok0 + tokA) * NTAG + tw * 5 + t] = sA[t] + bloc[t];
                d_feats[(tok0 + tokB) * NTAG + tw * 5 + t] = sB[t] + bloc[t];
            }
        }
    }
}

// ---------------- V1: per-chunk maxplus products (tree max) ----------------
__global__ __launch_bounds__(512) void viterbi_chunk_prod(const float* __restrict__ trans) {
    __shared__ float fsm[CLEN * NTAG];
    __shared__ float P[2][NTAG][NTAG];
    int c = blockIdx.x, tid = threadIdx.x;
    for (int i = tid; i < CLEN * NTAG; i += 512) fsm[i] = d_feats[c * CLEN * NTAG + i];
    __syncthreads();
    int j = tid / NTAG, k = tid % NTAG;
    bool act = (tid < NTAG * NTAG);
    float tr[NTAG];
    if (act) {
#pragma unroll
        for (int m = 0; m < NTAG; m++) tr[m] = trans[j * NTAG + m];
        P[0][j][k] = trans[j * NTAG + k] + fsm[j];
    }
    __syncthreads();
    int buf = 0;
    for (int t = 1; t < CLEN; t++) {
        if (act) {
            float v0 = -1e30f, v1 = -1e30f, v2 = -1e30f, v3 = -1e30f;
#pragma unroll
            for (int mm = 0; mm < 5; mm++) {
                v0 = fmaxf(v0, tr[4 * mm + 0] + P[buf][4 * mm + 0][k]);
                v1 = fmaxf(v1, tr[4 * mm + 1] + P[buf][4 * mm + 1][k]);
                v2 = fmaxf(v2, tr[4 * mm + 2] + P[buf][4 * mm + 2][k]);
                v3 = fmaxf(v3, tr[4 * mm + 3] + P[buf][4 * mm + 3][k]);
            }
            float v = fmaxf(fmaxf(v0, v1), fmaxf(v2, v3));
            P[buf ^ 1][j][k] = v + fsm[t * NTAG + j];
        }
        buf ^= 1;
        __syncthreads();
    }
    if (act) d_P[c * NTAG * NTAG + j * NTAG + k] = P[buf][j][k];
}

// ---------------- V2: sequential scan with prefetch ----------------
__global__ void viterbi_scan() {
    __shared__ float Ps[NTAG * NTAG];
    __shared__ float fvsm[NTAG];
    int lane = threadIdx.x;
    float cur[13], nx[13];
#pragma unroll
    for (int t = 0; t < 13; t++) {
        int i = lane + 32 * t;
        cur[t] = (i < NTAG * NTAG) ? d_P[i] : 0.f;
    }
    float fv = (lane == 18) ? 0.f : NEGV;
    for (int c = 0; c < NCHUNK; c++) {
#pragma unroll
        for (int t = 0; t < 13; t++) {
            int i = lane + 32 * t;
            if (i < NTAG * NTAG) Ps[i] = cur[t];
        }
        if (lane < NTAG) { d_fvs[c * NTAG + lane] = fv; fvsm[lane] = fv; }
        __syncwarp();
        if (c + 1 < NCHUNK) {
#pragma unroll
            for (int t = 0; t < 13; t++) {
                int i = lane + 32 * t;
                nx[t] = (i < NTAG * NTAG) ? d_P[(c + 1) * NTAG * NTAG + i] : 0.f;
            }
        }
        if (lane < NTAG) {
            float nf = -1e30f;
#pragma unroll
            for (int k = 0; k < NTAG; k++) nf = fmaxf(nf, Ps[lane * NTAG + k] + fvsm[k]);
            fv = nf;
        }
        __syncwarp();
#pragma unroll
        for (int t = 0; t < 13; t++) cur[t] = nx[t];
    }
}

// ---------------- V3: per-chunk forward + backpointers + chunk table (merged) ----------------
__global__ void viterbi_forward(const float* __restrict__ trans) {
    __shared__ float fsm[CLEN * NTAG];
    __shared__ unsigned char bsm[CLEN * NTAG];
    int c = blockIdx.x, lane = threadIdx.x;
    for (int i = lane; i < CLEN * NTAG; i += 32) fsm[i] = d_feats[c * CLEN * NTAG + i];
    __syncwarp();
    bool act = lane < NTAG;
    float tr[NTAG];
    if (act) {
#pragma unroll
        for (int m = 0; m < NTAG; m++) tr[m] = trans[lane * NTAG + m];
    }
    float fv = act ? d_fvs[c * NTAG + lane] : -1e30f;
    for (int t = 0; t < CLEN; t++) {
        float best = -1e30f;
        int bi = 0;
#pragma unroll
        for (int k = 0; k < NTAG; k++) {
            float v = __shfl_sync(0xffffffffu, fv, k);
            if (act) {
                v += tr[k];
                if (v > best) { best = v; bi = k; }
            }
        }
        if (act) {
            bsm[t * NTAG + lane] = (unsigned char)bi;
            fv = best + fsm[t * NTAG + lane];
        }
    }
    if (c == NCHUNK - 1 && act) d_finalfv[lane] = fv;
    __syncwarp();
    uint4* dst = (uint4*)(d_bps + c * CLEN * NTAG);
    const uint4* srcv = (const uint4*)bsm;
    for (int i = lane; i < (CLEN * NTAG) / 16; i += 32) dst[i] = srcv[i];
    if (act) {
        int x = lane;
        for (int t = CLEN - 1; t >= 0; t--) x = bsm[t * NTAG + x];
        d_Wc[c * NTAG + lane] = (unsigned char)x;
    }
}

// ---------------- B2: terminal argmax + boundary scan ----------------
__global__ void terminal_and_scan(const float* __restrict__ trans, float* __restrict__ out) {
    __shared__ unsigned char Wsm[NCHUNK * NTAG];
    int lane = threadIdx.x;
    const uint4* src = (const uint4*)d_Wc;
    for (int i = lane; i < (NCHUNK * NTAG) / 16; i += 32) ((uint4*)Wsm)[i] = src[i];
    float term = (lane < NTAG) ? d_finalfv[lane] + trans[19 * NTAG + lane] : -1e30f;
    __syncwarp();
    float best = -1e30f;
    int bi = 0;
#pragma unroll
    for (int k = 0; k < NTAG; k++) {
        float v = __shfl_sync(0xffffffffu, term, k);
        if (v > best) { best = v; bi = k; }
    }
    if (lane == 0) {
        out[0] = best;
        int r = bi;
        d_r[NCHUNK - 1] = (unsigned char)r;
        for (int c = NCHUNK - 1; c >= 1; c--) {
            r = Wsm[c * NTAG + r];
            d_r[c - 1] = (unsigned char)r;
        }
    }
}

// ---------------- B3: path emission ----------------
__global__ void backtrack_emit(float* __restrict__ out) {
    __shared__ unsigned char b[CLEN * NTAG];
    int c = blockIdx.x, lane = threadIdx.x;
    const uint4* src = (const uint4*)(d_bps + c * CLEN * NTAG);
    uint4* dstv = (uint4*)b;
    for (int i = lane; i < (CLEN * NTAG) / 16; i += 32) dstv[i] = src[i];
    __syncwarp();
    if (lane == 0) {
        int x = d_r[c];
        float* o = out + 1 + c * CLEN;
        for (int t = CLEN - 1; t >= 0; t--) {
            o[t] = (float)x;
            x = b[t * NTAG + x];
        }
    }
}

// ---------------- launch ----------------
extern "C" void kernel_launch(void* const* d_in, const int* in_sizes, int n_in,
                              void* d_out, int out_size) {
    const float* x      = (const float*)d_in[0];
    const float* w_ih_f = (const float*)d_in[1];
    const float* b_ih_f = (const float*)d_in[3];
    const float* b_hh_f = (const float*)d_in[4];
    const float* w_ih_b = (const float*)d_in[5];
    const float* b_ih_b = (const float*)d_in[7];
    const float* b_hh_b = (const float*)d_in[8];
    const float* w_tag  = (const float*)d_in[9];
    const float* b_tag  = (const float*)d_in[10];
    const float* trans  = (const float*)d_in[11];
    float* out = (float*)d_out;

    cudaFuncSetAttribute(gemm_fused, cudaFuncAttributeMaxDynamicSharedMemorySize, GSMEM);
    cudaFuncSetAttribute(feats_kernel, cudaFuncAttributeMaxDynamicSharedMemorySize,
                         FT_TOK * HIDC * (int)sizeof(float));

    prep_kernel<<<XBLK + WBLK, 256>>>(x, w_ih_f, w_ih_b, b_ih_f, b_hh_f, b_ih_b, b_hh_b);

    dim3 ggrid(NPACK / 96, NTOK / 128);
    gemm_fused<<<ggrid, 256, GSMEM>>>();

    feats_kernel<<<NTOK / FT_TOK, 256, FT_TOK * HIDC * sizeof(float)>>>(w_tag, b_tag);

    viterbi_chunk_prod<<<NCHUNK, 512>>>(trans);
    viterbi_scan<<<1, 32>>>();
    viterbi_forward<<<NCHUNK, 32>>>(trans);
    terminal_and_scan<<<1, 32>>>(trans, out);
    backtrack_emit<<<NCHUNK, 32>>>(out);
}